// round 7
// baseline (speedup 1.0000x reference)
#include <cuda_runtime.h>
#include <math.h>
#include <stdint.h>

#define NB    64
#define NPOMO 200
#define NPROB 200
#define NEMB  512
#define NHEAD 16
#define NHD   32
#define NNODE 201
#define QROWS 100   // q rows per attention block (2 tiles cover 200)

// ---------------- scratch (device globals) -----------------------------------
static __device__ float g_kbuf[(size_t)NB * NNODE * NEMB];
static __device__ float g_vbuf[(size_t)NB * NNODE * NEMB];
static __device__ float g_qbuf[(size_t)NB * NPOMO * NEMB];
static __device__ float g_obuf[(size_t)NB * NPOMO * NEMB];
static __device__ float g_mhbuf[(size_t)NB * NPOMO * NEMB];

__device__ __forceinline__ uint32_t f2tf(float x) {
    uint32_t r;
    asm("cvt.rna.tf32.f32 %0, %1;" : "=r"(r) : "f"(x));
    return r;
}
__device__ __forceinline__ uint32_t tfterm(float x, bool lo) {
    const uint32_t hi = f2tf(x);
    return lo ? f2tf(x - __uint_as_float(hi)) : hi;
}
__device__ __forceinline__ void mma8(float* c, const uint32_t* a, const uint32_t* b) {
    asm volatile(
        "mma.sync.aligned.m16n8k8.row.col.f32.tf32.tf32.f32 "
        "{%0,%1,%2,%3},{%4,%5,%6,%7},{%8,%9},{%0,%1,%2,%3};"
        : "+f"(c[0]), "+f"(c[1]), "+f"(c[2]), "+f"(c[3])
        : "r"(a[0]), "r"(a[1]), "r"(a[2]), "r"(a[3]), "r"(b[0]), "r"(b[1]));
}
__device__ __forceinline__ float4 ldg4(const float* p, bool ok, int rem) {
    float4 v = make_float4(0.f, 0.f, 0.f, 0.f);
    if (ok && rem > 0) {
        if (rem >= 4) v = *(const float4*)p;
        else { v.x = p[0]; if (rem > 1) v.y = p[1]; if (rem > 2) v.z = p[2]; }
    }
    return v;
}

// ---------------- TF32 tensor-core GEMM, 3-term compensated split ------------
// (unchanged from R6 — proven) C[z]=epi(alpha*(A@op(B) (+A2@op(B2))))
// epMode: 0 none, 1 +bias, 2 10*tanh+mask, 3 +mask
template <int BN>
__global__ void __launch_bounds__(256)
tf32_gemm(const float* __restrict__ A0, const float* __restrict__ B0,
          const float* __restrict__ A1, const float* __restrict__ B1,
          const float* __restrict__ bias, const float* __restrict__ mask,
          float* __restrict__ C, int M, int N, int K,
          int lda, int ldb, int ldc,
          long long aSb, long long aSh, long long bSb, long long bSh,
          long long cSb, long long cSh, long long mSb,
          int nbH, int transB, int epMode, int maskCols, float alpha)
{
    constexpr int SAST = 133, SBST = BN + 5, NW = BN / 32, BF4 = 4 * BN;
    __shared__ uint32_t sA[2][16][SAST];
    __shared__ uint32_t sB[2][16][SBST];

    const int t = threadIdx.x, lane = t & 31, wid = t >> 5;
    const int wm = wid & 1, wn = wid >> 1, g = lane >> 2, c4 = lane & 3;
    const int zb = blockIdx.z / nbH, zh = blockIdx.z - zb * nbH;
    const int m0 = blockIdx.y * 128, n0 = blockIdx.x * BN;

    const long long aOff = (long long)zb * aSb + (long long)zh * aSh;
    const long long bOff = (long long)zb * bSb + (long long)zh * bSh;
    float* Cp = C + (long long)zb * cSb + (long long)zh * cSh;
    const float* Mp = mask ? (mask + (long long)zb * mSb) : nullptr;

    float acc[4][NW][4];
#pragma unroll
    for (int mi = 0; mi < 4; mi++)
#pragma unroll
        for (int ni = 0; ni < NW; ni++)
#pragma unroll
            for (int j = 0; j < 4; j++) acc[mi][ni][j] = 0.f;

    const int nkt  = (K + 15) >> 4;
    const int nsrc = (A1 != nullptr) ? 2 : 1;
    const int nper = nkt * nsrc;
    const int ntt  = nper * 3;

    float4 va[2], vb[2];
    auto ldregs = [&](int tt) {
        const int rem = tt % nper;
        const int src = rem / nkt, k0 = (rem - src * nkt) * 16;
        const float* Ap = (src ? A1 : A0) + aOff;
        const float* Bp = (src ? B1 : B0) + bOff;
#pragma unroll
        for (int i = 0; i < 2; i++) {
            const int f = t + (i << 8), row = f >> 2, kq = (f & 3) << 2;
            va[i] = ldg4(Ap + (long long)(m0 + row) * lda + k0 + kq,
                         (m0 + row) < M, K - (k0 + kq));
        }
#pragma unroll
        for (int i = 0; i < 2; i++) {
            const int f = t + (i << 8);
            if (f >= BF4) { vb[i] = make_float4(0.f, 0.f, 0.f, 0.f); continue; }
            if (!transB) {
                const int kr = (BN == 128) ? (f >> 5) : (f >> 3);
                const int cq = (BN == 128) ? ((f & 31) << 2) : ((f & 7) << 2);
                vb[i] = ldg4(Bp + (long long)(k0 + kr) * ldb + n0 + cq,
                             (k0 + kr) < K, N - (n0 + cq));
            } else {
                const int nr = f >> 2, kq = (f & 3) << 2;
                vb[i] = ldg4(Bp + (long long)(n0 + nr) * ldb + k0 + kq,
                             (n0 + nr) < N, K - (k0 + kq));
            }
        }
    };
    auto stsmem = [&](int s, int tt) {
        const int term = tt / nper;
        const bool aLo = (term == 2), bLo = (term == 1);
#pragma unroll
        for (int i = 0; i < 2; i++) {
            const int f = t + (i << 8), row = f >> 2, kq = (f & 3) << 2;
            const float e[4] = {va[i].x, va[i].y, va[i].z, va[i].w};
#pragma unroll
            for (int j = 0; j < 4; j++) sA[s][kq + j][row] = tfterm(e[j], aLo);
        }
#pragma unroll
        for (int i = 0; i < 2; i++) {
            const int f = t + (i << 8);
            if (f >= BF4) continue;
            const float e[4] = {vb[i].x, vb[i].y, vb[i].z, vb[i].w};
#pragma unroll
            for (int j = 0; j < 4; j++) {
                int kk, cc;
                if (!transB) {
                    kk = (BN == 128) ? (f >> 5) : (f >> 3);
                    cc = ((BN == 128) ? ((f & 31) << 2) : ((f & 7) << 2)) + j;
                } else { kk = ((f & 3) << 2) + j; cc = f >> 2; }
                sB[s][kk][cc] = tfterm(e[j], bLo);
            }
        }
    };

    const int rbase = wm * 64 + g, cbase = wn * (BN / 4) + c4 * 2;
    auto compute = [&](int s) {
#pragma unroll
        for (int ks = 0; ks < 2; ks++) {
            const int k8 = ks * 8;
            uint32_t af[4][4], bf[NW][2];
#pragma unroll
            for (int mi = 0; mi < 4; mi++) {
                const int r = rbase + mi * 16;
                af[mi][0] = sA[s][k8 + c4][r];     af[mi][1] = sA[s][k8 + c4][r + 8];
                af[mi][2] = sA[s][k8 + c4 + 4][r]; af[mi][3] = sA[s][k8 + c4 + 4][r + 8];
            }
#pragma unroll
            for (int ni = 0; ni < NW; ni++) {
                const int cc = wn * (BN / 4) + ni * 8 + g;
                bf[ni][0] = sB[s][k8 + c4][cc]; bf[ni][1] = sB[s][k8 + c4 + 4][cc];
            }
#pragma unroll
            for (int mi = 0; mi < 4; mi++)
#pragma unroll
                for (int ni = 0; ni < NW; ni++) mma8(acc[mi][ni], af[mi], bf[ni]);
        }
    };

    ldregs(0); stsmem(0, 0); __syncthreads();
    for (int tt = 0; tt < ntt; tt++) {
        const int cur = tt & 1;
        if (tt + 1 < ntt) ldregs(tt + 1);
        compute(cur);
        __syncthreads();
        if (tt + 1 < ntt) { stsmem(1 - cur, tt + 1); __syncthreads(); }
    }

#pragma unroll
    for (int mi = 0; mi < 4; mi++)
#pragma unroll
        for (int ni = 0; ni < NW; ni++)
#pragma unroll
            for (int j = 0; j < 4; j++) {
                const int row = m0 + rbase + mi * 16 + ((j >> 1) << 3);
                const int col = n0 + cbase + ni * 8 + (j & 1);
                if (row >= M || col >= N) continue;
                float v = acc[mi][ni][j] * alpha;
                if (epMode == 1) v += bias[col];
                else if (epMode == 2) {
                    v = 10.f * tanhf(v);
                    if (col < maskCols) v += Mp[(long long)row * maskCols + col];
                } else if (epMode == 3) {
                    if (col < maskCols) v += Mp[(long long)row * maskCols + col];
                }
                Cp[(long long)row * ldc + col] = v;
            }
}

// ---------------- fused attention: S=QK^T/sqrt(D)+mask, softmax, O=S@V --------
// One block per (q-row-tile, b*16+h). All of S lives in smem; 3-term tf32 split
// for both MMAs (same numerics as the dense GEMMs).
// smem (floats): sK[32][209] @0 (6688) | sV[208][33] @6688 (6864)
//                | sQ[32][113] @13552 (3616) | sS[128][209] @17168 (26752)
#define ATTN_SMEM_FLOATS 43920
__global__ void __launch_bounds__(256)
attn_kernel(const float* __restrict__ qbuf, const float* __restrict__ kbuf,
            const float* __restrict__ vbuf, const float* __restrict__ ninf,
            float* __restrict__ obuf)
{
    extern __shared__ float sm[];
    float* sK = sm;
    float* sV = sm + 6688;
    float* sQ = sm + 13552;
    float* sS = sm + 17168;

    const int t = threadIdx.x, lane = t & 31, w = t >> 5;
    const int g = lane >> 2, c4 = lane & 3;
    const int z = blockIdx.y, b = z >> 4, h = z & 15;
    const int r0 = blockIdx.x * QROWS;

    const float* Kg = kbuf + ((long long)b * NNODE) * NEMB + h * NHD;
    const float* Vg = vbuf + ((long long)b * NNODE) * NEMB + h * NHD;
    const float* Qg = qbuf + ((long long)b * NPOMO + r0) * NEMB + h * NHD;
    const float* Mg = ninf + ((long long)b * NPOMO + r0) * NPROB;
    float* Og = obuf + ((long long)b * NPOMO + r0) * NEMB + h * NHD;

    // ---- stage K, V, Q into smem (coalesced global reads) ----
    for (int i = t; i < NNODE * NHD; i += 256) {
        const int node = i >> 5, d = i & 31;
        sK[d * 209 + node] = Kg[(long long)node * NEMB + d];
        sV[node * 33 + d]  = Vg[(long long)node * NEMB + d];
    }
    for (int i = t; i < (208 - NNODE) * NHD; i += 256) {      // pad nodes 201..207
        const int node = NNODE + (i >> 5), d = i & 31;
        sK[d * 209 + node] = 0.f;
        sV[node * 33 + d]  = 0.f;
    }
    for (int i = t; i < QROWS * NHD; i += 256) {
        const int row = i >> 5, d = i & 31;
        sQ[d * 113 + row] = Qg[(long long)row * NEMB + d];
    }
    for (int i = t; i < (112 - QROWS) * NHD; i += 256) {      // pad rows 100..111
        const int row = QROWS + (i >> 5), d = i & 31;
        sQ[d * 113 + row] = 0.f;
    }
    for (int i = t; i < (128 - QROWS) * 209; i += 256)        // zero S rows 100..127
        sS[QROWS * 209 + i] = 0.f;
    __syncthreads();

    // ---- phase 1: S = Q K^T / sqrt(D) + mask  (7 m-tiles x 26 n-tiles) ----
    const float isd = 0.17677669529663687f;
    for (int tile = w; tile < 7 * 26; tile += 8) {
        const int mt = tile / 26, nt = tile - mt * 26;
        const int rb = mt * 16, cb = nt * 8;
        float acc[4] = {0.f, 0.f, 0.f, 0.f};
#pragma unroll
        for (int kt = 0; kt < 4; kt++) {
            const int k8 = kt * 8;
            const float a[4] = { sQ[(k8 + c4) * 113 + rb + g],
                                 sQ[(k8 + c4) * 113 + rb + g + 8],
                                 sQ[(k8 + c4 + 4) * 113 + rb + g],
                                 sQ[(k8 + c4 + 4) * 113 + rb + g + 8] };
            const float bb[2] = { sK[(k8 + c4) * 209 + cb + g],
                                  sK[(k8 + c4 + 4) * 209 + cb + g] };
            uint32_t ah[4], al[4], bh[2], bl[2];
#pragma unroll
            for (int j = 0; j < 4; j++) { ah[j] = f2tf(a[j]); al[j] = f2tf(a[j] - __uint_as_float(ah[j])); }
#pragma unroll
            for (int j = 0; j < 2; j++) { bh[j] = f2tf(bb[j]); bl[j] = f2tf(bb[j] - __uint_as_float(bh[j])); }
            mma8(acc, ah, bh); mma8(acc, ah, bl); mma8(acc, al, bh);
        }
#pragma unroll
        for (int j = 0; j < 4; j++) {
            const int row = rb + g + ((j >> 1) << 3), col = cb + c4 * 2 + (j & 1);
            if (row < QROWS) {
                const float m = (col < NPROB) ? Mg[row * NPROB + col] : 0.f;
                sS[row * 209 + col] = acc[j] * isd + m;
            }
        }
    }
    __syncthreads();

    // ---- phase 2: row softmax in smem (also zero k-padding cols) ----
    for (int r = w; r < QROWS; r += 8) {
        float* rowp = sS + r * 209;
        float vals[7], mx = -INFINITY;
#pragma unroll
        for (int i = 0; i < 7; i++) {
            const int idx = lane + i * 32;
            vals[i] = (idx < NNODE) ? rowp[idx] : -INFINITY;
            mx = fmaxf(mx, vals[i]);
        }
#pragma unroll
        for (int o = 16; o > 0; o >>= 1) mx = fmaxf(mx, __shfl_xor_sync(~0u, mx, o));
        float sum = 0.f;
#pragma unroll
        for (int i = 0; i < 7; i++) {
            const int idx = lane + i * 32;
            vals[i] = (idx < NNODE) ? expf(vals[i] - mx) : 0.f;
            sum += vals[i];
        }
#pragma unroll
        for (int o = 16; o > 0; o >>= 1) sum += __shfl_xor_sync(~0u, sum, o);
        const float inv = 1.f / sum;
#pragma unroll
        for (int i = 0; i < 7; i++) {
            const int idx = lane + i * 32;
            if (idx < 208) rowp[idx] = (idx < NNODE) ? vals[i] * inv : 0.f;
        }
    }
    __syncthreads();

    // ---- phase 3: O = S @ V (8 m-tiles x 4 n-tiles; warp = (wm, wn)) ----
    {
        const int wm = w >> 2, wn = w & 3;
        const int cb = wn * 8;
        float acc[4][4];
#pragma unroll
        for (int i = 0; i < 4; i++)
#pragma unroll
            for (int j = 0; j < 4; j++) acc[i][j] = 0.f;

        for (int kt = 0; kt < 26; kt++) {
            const int k8 = kt * 8;
            const float bb[2] = { sV[(k8 + c4) * 33 + cb + g],
                                  sV[(k8 + c4 + 4) * 33 + cb + g] };
            uint32_t bh[2], bl[2];
#pragma unroll
            for (int j = 0; j < 2; j++) { bh[j] = f2tf(bb[j]); bl[j] = f2tf(bb[j] - __uint_as_float(bh[j])); }
#pragma unroll
            for (int i = 0; i < 4; i++) {
                const int rb = (wm + 2 * i) * 16;
                const float a[4] = { sS[(rb + g) * 209 + k8 + c4],
                                     sS[(rb + g + 8) * 209 + k8 + c4],
                                     sS[(rb + g) * 209 + k8 + c4 + 4],
                                     sS[(rb + g + 8) * 209 + k8 + c4 + 4] };
                uint32_t ah[4], al[4];
#pragma unroll
                for (int j = 0; j < 4; j++) { ah[j] = f2tf(a[j]); al[j] = f2tf(a[j] - __uint_as_float(ah[j])); }
                mma8(acc[i], ah, bh); mma8(acc[i], ah, bl); mma8(acc[i], al, bh);
            }
        }
#pragma unroll
        for (int i = 0; i < 4; i++) {
            const int rb = (wm + 2 * i) * 16;
#pragma unroll
            for (int j = 0; j < 4; j++) {
                const int row = rb + g + ((j >> 1) << 3), col = cb + c4 * 2 + (j & 1);
                if (row < QROWS) Og[(long long)row * NEMB + col] = acc[i][j];
            }
        }
    }
}

// ---------------- row softmax (final output) ----------------------------------
__global__ void __launch_bounds__(256)
softmax_kernel(float* __restrict__ X, int rows, int L, int stride)
{
    const int r = (blockIdx.x * blockDim.x + threadIdx.x) >> 5;
    const int lane = threadIdx.x & 31;
    if (r >= rows) return;
    float* rowp = X + (long long)r * stride;
    float vals[7], mx = -INFINITY;
#pragma unroll
    for (int i = 0; i < 7; i++) {
        const int idx = lane + i * 32;
        vals[i] = (idx < L) ? rowp[idx] : -INFINITY;
        mx = fmaxf(mx, vals[i]);
    }
#pragma unroll
    for (int o = 16; o > 0; o >>= 1) mx = fmaxf(mx, __shfl_xor_sync(~0u, mx, o));
    float sum = 0.f;
#pragma unroll
    for (int i = 0; i < 7; i++) {
        const int idx = lane + i * 32;
        vals[i] = (idx < L) ? expf(vals[i] - mx) : 0.f;
        sum += vals[i];
    }
#pragma unroll
    for (int o = 16; o > 0; o >>= 1) sum += __shfl_xor_sync(~0u, sum, o);
    const float inv = 1.f / sum;
#pragma unroll
    for (int i = 0; i < 7; i++) {
        const int idx = lane + i * 32;
        if (idx < L) rowp[idx] = vals[i] * inv;
    }
}

static inline int cdiv(int a, int b) { return (a + b - 1) / b; }

extern "C" void kernel_launch(void* const* d_in, const int* in_sizes, int n_in,
                              void* d_out, int out_size)
{
    const float* nodes = (const float*)d_in[0];
    const float* q1    = (const float*)d_in[1];
    const float* lastn = (const float*)d_in[2];
    const float* ninf  = (const float*)d_in[3];
    const float* Wqf   = (const float*)d_in[4];
    const float* Wql   = (const float*)d_in[5];
    const float* Wk    = (const float*)d_in[6];
    const float* Wv    = (const float*)d_in[7];
    const float* Wc    = (const float*)d_in[8];
    const float* bc    = (const float*)d_in[9];
    float* out = (float*)d_out;

    float *kbuf, *vbuf, *qbuf, *obuf, *mhbuf;
    cudaGetSymbolAddress((void**)&kbuf,  g_kbuf);
    cudaGetSymbolAddress((void**)&vbuf,  g_vbuf);
    cudaGetSymbolAddress((void**)&qbuf,  g_qbuf);
    cudaGetSymbolAddress((void**)&obuf,  g_obuf);
    cudaGetSymbolAddress((void**)&mhbuf, g_mhbuf);

    const dim3 blk(256);
    const float ise = 0.04419417382415922f;    // 1/sqrt(512)
    const int Mn = NB * NNODE, Mq = NB * NPOMO;

    // 1) K = nodes @ Wk
    tf32_gemm<128><<<dim3(4, cdiv(Mn, 128), 1), blk>>>(
        nodes, Wk, nullptr, nullptr, nullptr, nullptr, kbuf,
        Mn, NEMB, NEMB, NEMB, NEMB, NEMB, 0,0,0,0,0,0,0, 1, 0, 0, 0, 1.f);
    // 2) V = nodes @ Wv
    tf32_gemm<128><<<dim3(4, cdiv(Mn, 128), 1), blk>>>(
        nodes, Wv, nullptr, nullptr, nullptr, nullptr, vbuf,
        Mn, NEMB, NEMB, NEMB, NEMB, NEMB, 0,0,0,0,0,0,0, 1, 0, 0, 0, 1.f);
    // 3) Q = q1@Wqf + lastn@Wql (dual source)
    tf32_gemm<128><<<dim3(4, cdiv(Mq, 128), 1), blk>>>(
        q1, Wqf, lastn, Wql, nullptr, nullptr, qbuf,
        Mq, NEMB, NEMB, NEMB, NEMB, NEMB, 0,0,0,0,0,0,0, 1, 0, 0, 0, 1.f);
    // 4) fused attention: scores + mask + softmax + AV -> obuf
    {
        const int smemB = ATTN_SMEM_FLOATS * (int)sizeof(float);   // 175680
        cudaFuncSetAttribute(attn_kernel,
                             cudaFuncAttributeMaxDynamicSharedMemorySize, smemB);
        attn_kernel<<<dim3(NPOMO / QROWS, NB * NHEAD), blk, smemB>>>(
            qbuf, kbuf, vbuf, ninf, obuf);
    }
    // 5) mh = O @ Wc + bc
    tf32_gemm<128><<<dim3(4, cdiv(Mq, 128), 1), blk>>>(
        obuf, Wc, nullptr, nullptr, bc, nullptr, mhbuf,
        Mq, NEMB, NEMB, NEMB, NEMB, NEMB, 0,0,0,0,0,0,0, 1, 0, 1, 0, 1.f);
    // 6) out = 10*tanh(mh @ nodes[:,:200]^T / sqrt(EMB)) + ninf
    tf32_gemm<128><<<dim3(cdiv(NPROB, 128), cdiv(NPOMO, 128), NB), blk>>>(
        mhbuf, nodes, nullptr, nullptr, nullptr, ninf, out,
        NPOMO, NPROB, NEMB, NEMB, NEMB, NPROB,
        (long long)NPOMO * NEMB, 0,
        (long long)NNODE * NEMB, 0,
        (long long)NPOMO * NPROB, 0,
        (long long)NPOMO * NPROB,
        1, 1, 2, NPROB, ise);
    // 7) final softmax
    {
        const int rows = NB * NPOMO;
        softmax_kernel<<<cdiv(rows, 8), blk>>>(out, rows, NPROB, NPROB);
    }
}

// round 8
// speedup vs baseline: 1.2562x; 1.2562x over previous
#include <cuda_runtime.h>
#include <math.h>
#include <stdint.h>

#define NB    64
#define NPOMO 200
#define NPROB 200
#define NEMB  512
#define NHEAD 16
#define NHD   32
#define NNODE 201
#define QROWS 48

// ---------------- scratch (device globals) -----------------------------------
static __device__ float g_kbuf[(size_t)NB * NNODE * NEMB];
static __device__ float g_vbuf[(size_t)NB * NNODE * NEMB];
static __device__ float g_qbuf[(size_t)NB * NPOMO * NEMB];
static __device__ float g_obuf[(size_t)NB * NPOMO * NEMB];
static __device__ float g_mhbuf[(size_t)NB * NPOMO * NEMB];

__device__ __forceinline__ uint32_t f2tf(float x) {
    uint32_t r;
    asm("cvt.rna.tf32.f32 %0, %1;" : "=r"(r) : "f"(x));
    return r;
}
__device__ __forceinline__ void mma8(float* c, const uint32_t* a, const uint32_t* b) {
    asm volatile(
        "mma.sync.aligned.m16n8k8.row.col.f32.tf32.tf32.f32 "
        "{%0,%1,%2,%3},{%4,%5,%6,%7},{%8,%9},{%0,%1,%2,%3};"
        : "+f"(c[0]), "+f"(c[1]), "+f"(c[2]), "+f"(c[3])
        : "r"(a[0]), "r"(a[1]), "r"(a[2]), "r"(a[3]), "r"(b[0]), "r"(b[1]));
}
__device__ __forceinline__ float4 ldg4(const float* p, bool ok, int rem) {
    float4 v = make_float4(0.f, 0.f, 0.f, 0.f);
    if (ok && rem > 0) {
        if (rem >= 4) v = *(const float4*)p;
        else { v.x = p[0]; if (rem > 1) v.y = p[1]; if (rem > 2) v.z = p[2]; }
    }
    return v;
}

// ---------------- TF32 GEMM V2: hi/lo in smem, 3-term compute per stage -------
// BM=128, BN=128, BK=16, 256 threads (2x4 warps), double-buffered.
// smem u32 layout: sA[stage][term][16][133] then sB same; 17024 u32 = 68096 B.
#define SAx(s,tm,k,x) smU[(((s)*2+(tm))*16 + (k))*133 + (x)]
#define SBx(s,tm,k,x) smU[8512 + (((s)*2+(tm))*16 + (k))*133 + (x)]
#define GEMM_SMEM_BYTES (17024 * 4)

__global__ void __launch_bounds__(256)
tf32_gemm(const float* __restrict__ A0, const float* __restrict__ B0,
          const float* __restrict__ A1, const float* __restrict__ B1,
          const float* __restrict__ bias, const float* __restrict__ mask,
          float* __restrict__ C, int M, int N, int K,
          int lda, int ldb, int ldc,
          long long aSb, long long aSh, long long bSb, long long bSh,
          long long cSb, long long cSh, long long mSb,
          int nbH, int transB, int epMode, int maskCols, float alpha)
{
    extern __shared__ uint32_t smU[];

    const int t = threadIdx.x, lane = t & 31, wid = t >> 5;
    const int wm = wid & 1, wn = wid >> 1, g = lane >> 2, c4 = lane & 3;
    const int zb = blockIdx.z / nbH, zh = blockIdx.z - zb * nbH;
    const int m0 = blockIdx.y * 128, n0 = blockIdx.x * 128;

    const long long aOff = (long long)zb * aSb + (long long)zh * aSh;
    const long long bOff = (long long)zb * bSb + (long long)zh * bSh;
    float* Cp = C + (long long)zb * cSb + (long long)zh * cSh;
    const float* Mp = mask ? (mask + (long long)zb * mSb) : nullptr;

    float acc[4][4][4];
#pragma unroll
    for (int mi = 0; mi < 4; mi++)
#pragma unroll
        for (int ni = 0; ni < 4; ni++)
#pragma unroll
            for (int j = 0; j < 4; j++) acc[mi][ni][j] = 0.f;

    const int nkt  = (K + 15) >> 4;
    const int nper = nkt * ((A1 != nullptr) ? 2 : 1);

    float4 va[2], vb[2];
    auto ldregs = [&](int tt) {
        const int src = tt / nkt, k0 = (tt - src * nkt) * 16;
        const float* Ap = (src ? A1 : A0) + aOff;
        const float* Bp = (src ? B1 : B0) + bOff;
#pragma unroll
        for (int i = 0; i < 2; i++) {
            const int f = t + (i << 8), row = f >> 2, kq = (f & 3) << 2;
            va[i] = ldg4(Ap + (long long)(m0 + row) * lda + k0 + kq,
                         (m0 + row) < M, K - (k0 + kq));
        }
#pragma unroll
        for (int i = 0; i < 2; i++) {
            const int f = t + (i << 8);
            if (!transB) {
                const int kr = f >> 5, cq = (f & 31) << 2;
                vb[i] = ldg4(Bp + (long long)(k0 + kr) * ldb + n0 + cq,
                             (k0 + kr) < K, N - (n0 + cq));
            } else {
                const int nr = f >> 2, kq = (f & 3) << 2;
                vb[i] = ldg4(Bp + (long long)(n0 + nr) * ldb + k0 + kq,
                             (n0 + nr) < N, K - (k0 + kq));
            }
        }
    };
    auto stsmem = [&](int s) {
#pragma unroll
        for (int i = 0; i < 2; i++) {
            const int f = t + (i << 8), row = f >> 2, kq = (f & 3) << 2;
            const float e[4] = {va[i].x, va[i].y, va[i].z, va[i].w};
#pragma unroll
            for (int j = 0; j < 4; j++) {
                const uint32_t hi = f2tf(e[j]);
                SAx(s, 0, kq + j, row) = hi;
                SAx(s, 1, kq + j, row) = f2tf(e[j] - __uint_as_float(hi));
            }
        }
#pragma unroll
        for (int i = 0; i < 2; i++) {
            const int f = t + (i << 8);
            const float e[4] = {vb[i].x, vb[i].y, vb[i].z, vb[i].w};
#pragma unroll
            for (int j = 0; j < 4; j++) {
                int kk, cc;
                if (!transB) { kk = f >> 5; cc = ((f & 31) << 2) + j; }
                else         { kk = ((f & 3) << 2) + j; cc = f >> 2; }
                const uint32_t hi = f2tf(e[j]);
                SBx(s, 0, kk, cc) = hi;
                SBx(s, 1, kk, cc) = f2tf(e[j] - __uint_as_float(hi));
            }
        }
    };

    const int rbase = wm * 64 + g, cbase = wn * 32 + c4 * 2;
    auto compute = [&](int s) {
#pragma unroll
        for (int ks = 0; ks < 2; ks++) {
            const int k8 = ks * 8;
            uint32_t bh[4][2], bl[4][2];
#pragma unroll
            for (int ni = 0; ni < 4; ni++) {
                const int cc = wn * 32 + ni * 8 + g;
                bh[ni][0] = SBx(s, 0, k8 + c4, cc);
                bh[ni][1] = SBx(s, 0, k8 + c4 + 4, cc);
                bl[ni][0] = SBx(s, 1, k8 + c4, cc);
                bl[ni][1] = SBx(s, 1, k8 + c4 + 4, cc);
            }
#pragma unroll
            for (int mi = 0; mi < 4; mi++) {
                const int r = rbase + mi * 16;
                uint32_t ah[4], al[4];
                ah[0] = SAx(s, 0, k8 + c4, r);     ah[1] = SAx(s, 0, k8 + c4, r + 8);
                ah[2] = SAx(s, 0, k8 + c4 + 4, r); ah[3] = SAx(s, 0, k8 + c4 + 4, r + 8);
                al[0] = SAx(s, 1, k8 + c4, r);     al[1] = SAx(s, 1, k8 + c4, r + 8);
                al[2] = SAx(s, 1, k8 + c4 + 4, r); al[3] = SAx(s, 1, k8 + c4 + 4, r + 8);
#pragma unroll
                for (int ni = 0; ni < 4; ni++) {
                    mma8(acc[mi][ni], ah, bh[ni]);
                    mma8(acc[mi][ni], ah, bl[ni]);
                    mma8(acc[mi][ni], al, bh[ni]);
                }
            }
        }
    };

    ldregs(0); stsmem(0); __syncthreads();
    for (int tt = 0; tt < nper; tt++) {
        const int cur = tt & 1;
        if (tt + 1 < nper) ldregs(tt + 1);
        compute(cur);
        __syncthreads();
        if (tt + 1 < nper) { stsmem(1 - cur); __syncthreads(); }
    }

    // ---- epilogue ----
#pragma unroll
    for (int mi = 0; mi < 4; mi++)
#pragma unroll
        for (int ni = 0; ni < 4; ni++)
#pragma unroll
            for (int j = 0; j < 4; j++) {
                const int row = m0 + rbase + mi * 16 + ((j >> 1) << 3);
                const int col = n0 + cbase + ni * 8 + (j & 1);
                if (row >= M || col >= N) continue;
                float v = acc[mi][ni][j] * alpha;
                if (epMode == 1) v += bias[col];
                else if (epMode == 2) {
                    v = 10.f * tanhf(v);
                    if (col < maskCols) v += Mp[(long long)row * maskCols + col];
                } else if (epMode == 3) {
                    if (col < maskCols) v += Mp[(long long)row * maskCols + col];
                }
                Cp[(long long)row * ldc + col] = v;
            }
}

// ---------------- fused attention V2: pre-split smem, cvt-free inner loops ----
// One block per (48-q-row tile, b*16+h). smem offsets in u32:
#define A_KH 0        // [32][209]  K^T hi
#define A_KL 6688     // [32][209]  K^T lo
#define A_VH 13376    // [208][33]  V hi
#define A_VL 20240    // [208][33]  V lo
#define A_QH 27104    // [32][52]   Q^T hi
#define A_QL 28768    // [32][52]   Q^T lo
#define A_SH 30432    // [48][209]  scores fp32 -> weights hi
#define A_SL 40464    // [48][209]  weights lo
#define ATTN_SMEM_BYTES (50496 * 4)

__global__ void __launch_bounds__(256)
attn_kernel(const float* __restrict__ qbuf, const float* __restrict__ kbuf,
            const float* __restrict__ vbuf, const float* __restrict__ ninf,
            float* __restrict__ obuf)
{
    extern __shared__ uint32_t sm[];
    const int t = threadIdx.x, lane = t & 31, w = t >> 5;
    const int g = lane >> 2, c4 = lane & 3;
    const int z = blockIdx.y, b = z >> 4, h = z & 15;
    const int r0 = blockIdx.x * QROWS;

    const float* Kg = kbuf + ((long long)b * NNODE) * NEMB + h * NHD;
    const float* Vg = vbuf + ((long long)b * NNODE) * NEMB + h * NHD;
    const float* Qg = qbuf + ((long long)b * NPOMO + r0) * NEMB + h * NHD;
    const float* Mg = ninf + ((long long)b * NPOMO + r0) * NPROB;
    float* Og = obuf + ((long long)b * NPOMO + r0) * NEMB + h * NHD;

    // ---- stage K, V (zero-pad nodes 201..207), pre-split hi/lo ----
    for (int i = t; i < 208 * 32; i += 256) {
        const int node = i >> 5, d = i & 31;
        const float kv = (node < NNODE) ? Kg[(long long)node * NEMB + d] : 0.f;
        const float vv = (node < NNODE) ? Vg[(long long)node * NEMB + d] : 0.f;
        const uint32_t kh = f2tf(kv), vh = f2tf(vv);
        sm[A_KH + d * 209 + node] = kh;
        sm[A_KL + d * 209 + node] = f2tf(kv - __uint_as_float(kh));
        sm[A_VH + node * 33 + d] = vh;
        sm[A_VL + node * 33 + d] = f2tf(vv - __uint_as_float(vh));
    }
    // ---- stage Q (zero rows beyond NPOMO) ----
    for (int i = t; i < QROWS * 32; i += 256) {
        const int row = i >> 5, d = i & 31;
        const float qv = (r0 + row < NPOMO) ? Qg[(long long)row * NEMB + d] : 0.f;
        const uint32_t qh = f2tf(qv);
        sm[A_QH + d * 52 + row] = qh;
        sm[A_QL + d * 52 + row] = f2tf(qv - __uint_as_float(qh));
    }
    __syncthreads();

    // ---- phase 1: S = Q K^T / sqrt(D) + mask   (3 m-tiles x 26 n-tiles) ----
    const float isd = 0.17677669529663687f;
    float* Sf = (float*)(sm + A_SH);
    for (int tile = w; tile < 3 * 26; tile += 8) {
        const int mt = tile / 26, nt = tile - mt * 26;
        const int rb = mt * 16, cb = nt * 8;
        float acc[4] = {0.f, 0.f, 0.f, 0.f};
#pragma unroll
        for (int kt = 0; kt < 4; kt++) {
            const int k8 = kt * 8;
            uint32_t ah[4], al[4], bh[2], bl[2];
            ah[0] = sm[A_QH + (k8 + c4) * 52 + rb + g];
            ah[1] = sm[A_QH + (k8 + c4) * 52 + rb + g + 8];
            ah[2] = sm[A_QH + (k8 + c4 + 4) * 52 + rb + g];
            ah[3] = sm[A_QH + (k8 + c4 + 4) * 52 + rb + g + 8];
            al[0] = sm[A_QL + (k8 + c4) * 52 + rb + g];
            al[1] = sm[A_QL + (k8 + c4) * 52 + rb + g + 8];
            al[2] = sm[A_QL + (k8 + c4 + 4) * 52 + rb + g];
            al[3] = sm[A_QL + (k8 + c4 + 4) * 52 + rb + g + 8];
            bh[0] = sm[A_KH + (k8 + c4) * 209 + cb + g];
            bh[1] = sm[A_KH + (k8 + c4 + 4) * 209 + cb + g];
            bl[0] = sm[A_KL + (k8 + c4) * 209 + cb + g];
            bl[1] = sm[A_KL + (k8 + c4 + 4) * 209 + cb + g];
            mma8(acc, ah, bh); mma8(acc, ah, bl); mma8(acc, al, bh);
        }
#pragma unroll
        for (int j = 0; j < 4; j++) {
            const int row = rb + g + ((j >> 1) << 3), col = cb + c4 * 2 + (j & 1);
            const float m = (col < NPROB && r0 + row < NPOMO)
                          ? Mg[row * NPROB + col] : 0.f;
            Sf[row * 209 + col] = acc[j] * isd + m;
        }
    }
    __syncthreads();

    // ---- phase 2: row softmax; write weights as hi/lo tf32 planes ----
    for (int r = w; r < QROWS; r += 8) {
        float* rowp = Sf + r * 209;
        float vals[7], mx = -INFINITY;
#pragma unroll
        for (int i = 0; i < 7; i++) {
            const int idx = lane + i * 32;
            vals[i] = (idx < NNODE) ? rowp[idx] : -INFINITY;
            mx = fmaxf(mx, vals[i]);
        }
#pragma unroll
        for (int o = 16; o > 0; o >>= 1) mx = fmaxf(mx, __shfl_xor_sync(~0u, mx, o));
        float sum = 0.f;
#pragma unroll
        for (int i = 0; i < 7; i++) {
            const int idx = lane + i * 32;
            vals[i] = (idx < NNODE) ? expf(vals[i] - mx) : 0.f;
            sum += vals[i];
        }
#pragma unroll
        for (int o = 16; o > 0; o >>= 1) sum += __shfl_xor_sync(~0u, sum, o);
        const float inv = 1.f / sum;
#pragma unroll
        for (int i = 0; i < 7; i++) {
            const int idx = lane + i * 32;
            if (idx < 208) {
                const float wv = (idx < NNODE) ? vals[i] * inv : 0.f;
                const uint32_t hi = f2tf(wv);
                sm[A_SH + r * 209 + idx] = hi;
                sm[A_SL + r * 209 + idx] = f2tf(wv - __uint_as_float(hi));
            }
        }
    }
    __syncthreads();

    // ---- phase 3: O = S @ V   (3 m-tiles x 4 n-tiles = 12 warp tiles) ----
    for (int tile = w; tile < 12; tile += 8) {
        const int mt = tile >> 2, nt = tile & 3;
        const int rb = mt * 16, cb = nt * 8;
        float acc[4] = {0.f, 0.f, 0.f, 0.f};
        for (int kt = 0; kt < 26; kt++) {
            const int k8 = kt * 8;
            uint32_t ah[4], al[4], bh[2], bl[2];
            ah[0] = sm[A_SH + (rb + g) * 209 + k8 + c4];
            ah[1] = sm[A_SH + (rb + g + 8) * 209 + k8 + c4];
            ah[2] = sm[A_SH + (rb + g) * 209 + k8 + c4 + 4];
            ah[3] = sm[A_SH + (rb + g + 8) * 209 + k8 + c4 + 4];
            al[0] = sm[A_SL + (rb + g) * 209 + k8 + c4];
            al[1] = sm[A_SL + (rb + g + 8) * 209 + k8 + c4];
            al[2] = sm[A_SL + (rb + g) * 209 + k8 + c4 + 4];
            al[3] = sm[A_SL + (rb + g + 8) * 209 + k8 + c4 + 4];
            bh[0] = sm[A_VH + (k8 + c4) * 33 + cb + g];
            bh[1] = sm[A_VH + (k8 + c4 + 4) * 33 + cb + g];
            bl[0] = sm[A_VL + (k8 + c4) * 33 + cb + g];
            bl[1] = sm[A_VL + (k8 + c4 + 4) * 33 + cb + g];
            mma8(acc, ah, bh); mma8(acc, ah, bl); mma8(acc, al, bh);
        }
#pragma unroll
        for (int j = 0; j < 4; j++) {
            const int row = rb + g + ((j >> 1) << 3), col = cb + c4 * 2 + (j & 1);
            if (r0 + row < NPOMO) Og[(long long)row * NEMB + col] = acc[j];
        }
    }
}

// ---------------- row softmax (final output) ----------------------------------
__global__ void __launch_bounds__(256)
softmax_kernel(float* __restrict__ X, int rows, int L, int stride)
{
    const int r = (blockIdx.x * blockDim.x + threadIdx.x) >> 5;
    const int lane = threadIdx.x & 31;
    if (r >= rows) return;
    float* rowp = X + (long long)r * stride;
    float vals[7], mx = -INFINITY;
#pragma unroll
    for (int i = 0; i < 7; i++) {
        const int idx = lane + i * 32;
        vals[i] = (idx < L) ? rowp[idx] : -INFINITY;
        mx = fmaxf(mx, vals[i]);
    }
#pragma unroll
    for (int o = 16; o > 0; o >>= 1) mx = fmaxf(mx, __shfl_xor_sync(~0u, mx, o));
    float sum = 0.f;
#pragma unroll
    for (int i = 0; i < 7; i++) {
        const int idx = lane + i * 32;
        vals[i] = (idx < L) ? expf(vals[i] - mx) : 0.f;
        sum += vals[i];
    }
#pragma unroll
    for (int o = 16; o > 0; o >>= 1) sum += __shfl_xor_sync(~0u, sum, o);
    const float inv = 1.f / sum;
#pragma unroll
    for (int i = 0; i < 7; i++) {
        const int idx = lane + i * 32;
        if (idx < L) rowp[idx] = vals[i] * inv;
    }
}

static inline int cdiv(int a, int b) { return (a + b - 1) / b; }

extern "C" void kernel_launch(void* const* d_in, const int* in_sizes, int n_in,
                              void* d_out, int out_size)
{
    const float* nodes = (const float*)d_in[0];
    const float* q1    = (const float*)d_in[1];
    const float* lastn = (const float*)d_in[2];
    const float* ninf  = (const float*)d_in[3];
    const float* Wqf   = (const float*)d_in[4];
    const float* Wql   = (const float*)d_in[5];
    const float* Wk    = (const float*)d_in[6];
    const float* Wv    = (const float*)d_in[7];
    const float* Wc    = (const float*)d_in[8];
    const float* bc    = (const float*)d_in[9];
    float* out = (float*)d_out;

    float *kbuf, *vbuf, *qbuf, *obuf, *mhbuf;
    cudaGetSymbolAddress((void**)&kbuf,  g_kbuf);
    cudaGetSymbolAddress((void**)&vbuf,  g_vbuf);
    cudaGetSymbolAddress((void**)&qbuf,  g_qbuf);
    cudaGetSymbolAddress((void**)&obuf,  g_obuf);
    cudaGetSymbolAddress((void**)&mhbuf, g_mhbuf);

    cudaFuncSetAttribute(tf32_gemm, cudaFuncAttributeMaxDynamicSharedMemorySize,
                         GEMM_SMEM_BYTES);
    cudaFuncSetAttribute(attn_kernel, cudaFuncAttributeMaxDynamicSharedMemorySize,
                         ATTN_SMEM_BYTES);

    const dim3 blk(256);
    const float ise = 0.04419417382415922f;    // 1/sqrt(512)
    const int Mn = NB * NNODE, Mq = NB * NPOMO;

    // 1) K = nodes @ Wk
    tf32_gemm<<<dim3(4, cdiv(Mn, 128), 1), blk, GEMM_SMEM_BYTES>>>(
        nodes, Wk, nullptr, nullptr, nullptr, nullptr, kbuf,
        Mn, NEMB, NEMB, NEMB, NEMB, NEMB, 0,0,0,0,0,0,0, 1, 0, 0, 0, 1.f);
    // 2) V = nodes @ Wv
    tf32_gemm<<<dim3(4, cdiv(Mn, 128), 1), blk, GEMM_SMEM_BYTES>>>(
        nodes, Wv, nullptr, nullptr, nullptr, nullptr, vbuf,
        Mn, NEMB, NEMB, NEMB, NEMB, NEMB, 0,0,0,0,0,0,0, 1, 0, 0, 0, 1.f);
    // 3) Q = q1@Wqf + lastn@Wql (dual source)
    tf32_gemm<<<dim3(4, cdiv(Mq, 128), 1), blk, GEMM_SMEM_BYTES>>>(
        q1, Wqf, lastn, Wql, nullptr, nullptr, qbuf,
        Mq, NEMB, NEMB, NEMB, NEMB, NEMB, 0,0,0,0,0,0,0, 1, 0, 0, 0, 1.f);
    // 4) fused attention: scores + mask + softmax + AV -> obuf
    attn_kernel<<<dim3(cdiv(NPOMO, QROWS), NB * NHEAD), blk, ATTN_SMEM_BYTES>>>(
        qbuf, kbuf, vbuf, ninf, obuf);
    // 5) mh = O @ Wc + bc
    tf32_gemm<<<dim3(4, cdiv(Mq, 128), 1), blk, GEMM_SMEM_BYTES>>>(
        obuf, Wc, nullptr, nullptr, bc, nullptr, mhbuf,
        Mq, NEMB, NEMB, NEMB, NEMB, NEMB, 0,0,0,0,0,0,0, 1, 0, 1, 0, 1.f);
    // 6) out = 10*tanh(mh @ nodes[:,:200]^T / sqrt(EMB)) + ninf
    tf32_gemm<<<dim3(cdiv(NPROB, 128), cdiv(NPOMO, 128), NB), blk, GEMM_SMEM_BYTES>>>(
        mhbuf, nodes, nullptr, nullptr, nullptr, ninf, out,
        NPOMO, NPROB, NEMB, NEMB, NEMB, NPROB,
        (long long)NPOMO * NEMB, 0,
        (long long)NNODE * NEMB, 0,
        (long long)NPOMO * NPROB, 0,
        (long long)NPOMO * NPROB,
        1, 1, 2, NPROB, ise);
    // 7) final softmax
    {
        const int rows = NB * NPOMO;
        softmax_kernel<<<cdiv(rows, 8), blk>>>(out, rows, NPROB, NPROB);
    }
}

// round 9
// speedup vs baseline: 1.3376x; 1.0648x over previous
#include <cuda_runtime.h>
#include <math.h>
#include <stdint.h>

#define NB    64
#define NPOMO 200
#define NPROB 200
#define NEMB  512
#define NHEAD 16
#define NHD   32
#define NNODE 201
#define QROWS 64

// ---------------- scratch (device globals) -----------------------------------
static __device__ float g_kbuf[(size_t)NB * NNODE * NEMB];
static __device__ float g_vbuf[(size_t)NB * NNODE * NEMB];
static __device__ float g_qbuf[(size_t)NB * NPOMO * NEMB];
static __device__ float g_obuf[(size_t)NB * NPOMO * NEMB];
static __device__ float g_mhbuf[(size_t)NB * NPOMO * NEMB];

__device__ __forceinline__ uint32_t f2tf(float x) {
    uint32_t r;
    asm("cvt.rna.tf32.f32 %0, %1;" : "=r"(r) : "f"(x));
    return r;
}
__device__ __forceinline__ void mma8(float* c, const uint32_t* a, const uint32_t* b) {
    asm volatile(
        "mma.sync.aligned.m16n8k8.row.col.f32.tf32.tf32.f32 "
        "{%0,%1,%2,%3},{%4,%5,%6,%7},{%8,%9},{%0,%1,%2,%3};"
        : "+f"(c[0]), "+f"(c[1]), "+f"(c[2]), "+f"(c[3])
        : "r"(a[0]), "r"(a[1]), "r"(a[2]), "r"(a[3]), "r"(b[0]), "r"(b[1]));
}
__device__ __forceinline__ float4 ldg4(const float* p, bool ok, int rem) {
    float4 v = make_float4(0.f, 0.f, 0.f, 0.f);
    if (ok && rem > 0) {
        if (rem >= 4) v = *(const float4*)p;
        else { v.x = p[0]; if (rem > 1) v.y = p[1]; if (rem > 2) v.z = p[2]; }
    }
    return v;
}

// ---------------- TF32 GEMM V2: hi/lo in smem, 3-term compute per stage -------
// BM=128, BN=128, BK=16, 256 threads (2x4 warps), double-buffered. (proven R8)
#define SAx(s,tm,k,x) smU[(((s)*2+(tm))*16 + (k))*133 + (x)]
#define SBx(s,tm,k,x) smU[8512 + (((s)*2+(tm))*16 + (k))*133 + (x)]
#define GEMM_SMEM_BYTES (17024 * 4)

__global__ void __launch_bounds__(256)
tf32_gemm(const float* __restrict__ A0, const float* __restrict__ B0,
          const float* __restrict__ A1, const float* __restrict__ B1,
          const float* __restrict__ bias, const float* __restrict__ mask,
          float* __restrict__ C, int M, int N, int K,
          int lda, int ldb, int ldc,
          long long aSb, long long aSh, long long bSb, long long bSh,
          long long cSb, long long cSh, long long mSb,
          int nbH, int transB, int epMode, int maskCols, float alpha)
{
    extern __shared__ uint32_t smU[];

    const int t = threadIdx.x, lane = t & 31, wid = t >> 5;
    const int wm = wid & 1, wn = wid >> 1, g = lane >> 2, c4 = lane & 3;
    const int zb = blockIdx.z / nbH, zh = blockIdx.z - zb * nbH;
    const int m0 = blockIdx.y * 128, n0 = blockIdx.x * 128;

    const long long aOff = (long long)zb * aSb + (long long)zh * aSh;
    const long long bOff = (long long)zb * bSb + (long long)zh * bSh;
    float* Cp = C + (long long)zb * cSb + (long long)zh * cSh;
    const float* Mp = mask ? (mask + (long long)zb * mSb) : nullptr;

    float acc[4][4][4];
#pragma unroll
    for (int mi = 0; mi < 4; mi++)
#pragma unroll
        for (int ni = 0; ni < 4; ni++)
#pragma unroll
            for (int j = 0; j < 4; j++) acc[mi][ni][j] = 0.f;

    const int nkt  = (K + 15) >> 4;
    const int nper = nkt * ((A1 != nullptr) ? 2 : 1);

    float4 va[2], vb[2];
    auto ldregs = [&](int tt) {
        const int src = tt / nkt, k0 = (tt - src * nkt) * 16;
        const float* Ap = (src ? A1 : A0) + aOff;
        const float* Bp = (src ? B1 : B0) + bOff;
#pragma unroll
        for (int i = 0; i < 2; i++) {
            const int f = t + (i << 8), row = f >> 2, kq = (f & 3) << 2;
            va[i] = ldg4(Ap + (long long)(m0 + row) * lda + k0 + kq,
                         (m0 + row) < M, K - (k0 + kq));
        }
#pragma unroll
        for (int i = 0; i < 2; i++) {
            const int f = t + (i << 8);
            if (!transB) {
                const int kr = f >> 5, cq = (f & 31) << 2;
                vb[i] = ldg4(Bp + (long long)(k0 + kr) * ldb + n0 + cq,
                             (k0 + kr) < K, N - (n0 + cq));
            } else {
                const int nr = f >> 2, kq = (f & 3) << 2;
                vb[i] = ldg4(Bp + (long long)(n0 + nr) * ldb + k0 + kq,
                             (n0 + nr) < N, K - (k0 + kq));
            }
        }
    };
    auto stsmem = [&](int s) {
#pragma unroll
        for (int i = 0; i < 2; i++) {
            const int f = t + (i << 8), row = f >> 2, kq = (f & 3) << 2;
            const float e[4] = {va[i].x, va[i].y, va[i].z, va[i].w};
#pragma unroll
            for (int j = 0; j < 4; j++) {
                const uint32_t hi = f2tf(e[j]);
                SAx(s, 0, kq + j, row) = hi;
                SAx(s, 1, kq + j, row) = f2tf(e[j] - __uint_as_float(hi));
            }
        }
#pragma unroll
        for (int i = 0; i < 2; i++) {
            const int f = t + (i << 8);
            const float e[4] = {vb[i].x, vb[i].y, vb[i].z, vb[i].w};
#pragma unroll
            for (int j = 0; j < 4; j++) {
                int kk, cc;
                if (!transB) { kk = f >> 5; cc = ((f & 31) << 2) + j; }
                else         { kk = ((f & 3) << 2) + j; cc = f >> 2; }
                const uint32_t hi = f2tf(e[j]);
                SBx(s, 0, kk, cc) = hi;
                SBx(s, 1, kk, cc) = f2tf(e[j] - __uint_as_float(hi));
            }
        }
    };

    const int rbase = wm * 64 + g, cbase = wn * 32 + c4 * 2;
    auto compute = [&](int s) {
#pragma unroll
        for (int ks = 0; ks < 2; ks++) {
            const int k8 = ks * 8;
            uint32_t bh[4][2], bl[4][2];
#pragma unroll
            for (int ni = 0; ni < 4; ni++) {
                const int cc = wn * 32 + ni * 8 + g;
                bh[ni][0] = SBx(s, 0, k8 + c4, cc);
                bh[ni][1] = SBx(s, 0, k8 + c4 + 4, cc);
                bl[ni][0] = SBx(s, 1, k8 + c4, cc);
                bl[ni][1] = SBx(s, 1, k8 + c4 + 4, cc);
            }
#pragma unroll
            for (int mi = 0; mi < 4; mi++) {
                const int r = rbase + mi * 16;
                uint32_t ah[4], al[4];
                ah[0] = SAx(s, 0, k8 + c4, r);     ah[1] = SAx(s, 0, k8 + c4, r + 8);
                ah[2] = SAx(s, 0, k8 + c4 + 4, r); ah[3] = SAx(s, 0, k8 + c4 + 4, r + 8);
                al[0] = SAx(s, 1, k8 + c4, r);     al[1] = SAx(s, 1, k8 + c4, r + 8);
                al[2] = SAx(s, 1, k8 + c4 + 4, r); al[3] = SAx(s, 1, k8 + c4 + 4, r + 8);
#pragma unroll
                for (int ni = 0; ni < 4; ni++) {
                    mma8(acc[mi][ni], ah, bh[ni]);
                    mma8(acc[mi][ni], ah, bl[ni]);
                    mma8(acc[mi][ni], al, bh[ni]);
                }
            }
        }
    };

    ldregs(0); stsmem(0); __syncthreads();
    for (int tt = 0; tt < nper; tt++) {
        const int cur = tt & 1;
        if (tt + 1 < nper) ldregs(tt + 1);
        compute(cur);
        __syncthreads();
        if (tt + 1 < nper) { stsmem(1 - cur); __syncthreads(); }
    }

#pragma unroll
    for (int mi = 0; mi < 4; mi++)
#pragma unroll
        for (int ni = 0; ni < 4; ni++)
#pragma unroll
            for (int j = 0; j < 4; j++) {
                const int row = m0 + rbase + mi * 16 + ((j >> 1) << 3);
                const int col = n0 + cbase + ni * 8 + (j & 1);
                if (row >= M || col >= N) continue;
                float v = acc[mi][ni][j] * alpha;
                if (epMode == 1) v += bias[col];
                else if (epMode == 2) {
                    v = 10.f * tanhf(v);
                    if (col < maskCols) v += Mp[(long long)row * maskCols + col];
                } else if (epMode == 3) {
                    if (col < maskCols) v += Mp[(long long)row * maskCols + col];
                }
                Cp[(long long)row * ldc + col] = v;
            }
}

// ---------------- fused attention V3: 512 thr, amortized fragments ------------
// One block per (64-q-row tile, b*16+h). 16 warps. smem offsets in u32:
#define A_KH 0        // [32][209]  K^T hi
#define A_KL 6688     // [32][209]  K^T lo
#define A_VH 13376    // [208][33]  V hi
#define A_VL 20240    // [208][33]  V lo
#define A_QH 27104    // [32][66]   Q^T hi
#define A_QL 29216    // [32][66]   Q^T lo
#define A_SH 31328    // [64][209]  scores fp32 -> weights hi
#define A_SL 44704    // [64][209]  weights lo
#define ATTN_SMEM_BYTES (58080 * 4)   // 232320 <= 232448

__global__ void __launch_bounds__(512)
attn_kernel(const float* __restrict__ qbuf, const float* __restrict__ kbuf,
            const float* __restrict__ vbuf, const float* __restrict__ ninf,
            float* __restrict__ obuf)
{
    extern __shared__ uint32_t sm[];
    const int t = threadIdx.x, lane = t & 31, w = t >> 5;
    const int g = lane >> 2, c4 = lane & 3;
    const int z = blockIdx.y, b = z >> 4, h = z & 15;
    const int r0 = blockIdx.x * QROWS;

    const float* Kg = kbuf + ((long long)b * NNODE) * NEMB + h * NHD;
    const float* Vg = vbuf + ((long long)b * NNODE) * NEMB + h * NHD;
    const float* Qg = qbuf + ((long long)b * NPOMO + r0) * NEMB + h * NHD;
    const float* Mg = ninf + ((long long)b * NPOMO + r0) * NPROB;
    float* Og = obuf + ((long long)b * NPOMO + r0) * NEMB + h * NHD;

    // ---- stage K, V (pad nodes 201..207 with 0), pre-split hi/lo ----
    for (int i = t; i < 208 * 32; i += 512) {
        const int node = i >> 5, d = i & 31;
        const float kv = (node < NNODE) ? Kg[(long long)node * NEMB + d] : 0.f;
        const float vv = (node < NNODE) ? Vg[(long long)node * NEMB + d] : 0.f;
        const uint32_t kh = f2tf(kv), vh = f2tf(vv);
        sm[A_KH + d * 209 + node] = kh;
        sm[A_KL + d * 209 + node] = f2tf(kv - __uint_as_float(kh));
        sm[A_VH + node * 33 + d] = vh;
        sm[A_VL + node * 33 + d] = f2tf(vv - __uint_as_float(vh));
    }
    // ---- stage Q rows 0..63 (zero rows beyond NPOMO) ----
    for (int i = t; i < QROWS * 32; i += 512) {
        const int row = i >> 5, d = i & 31;
        const float qv = (r0 + row < NPOMO) ? Qg[(long long)row * NEMB + d] : 0.f;
        const uint32_t qh = f2tf(qv);
        sm[A_QH + d * 66 + row] = qh;
        sm[A_QL + d * 66 + row] = f2tf(qv - __uint_as_float(qh));
    }
    __syncthreads();

    // ---- phase 1: S = Q K^T / sqrt(D) + mask ----
    // 16 jobs: warp = (mt = w>>2, n-group = w&3). n-groups of {7,7,6,6} tiles.
    const float isd = 0.17677669529663687f;
    float* Sf = (float*)(sm + A_SH);
    {
        const int mt = w >> 2, nq = w & 3;
        const int rb = mt * 16;
        const int nstart = (nq <= 1) ? nq * 7 : 14 + (nq - 2) * 6;
        const int ncnt   = (nq <= 1) ? 7 : 6;
        float acc[7][4];
#pragma unroll
        for (int ni = 0; ni < 7; ni++)
#pragma unroll
            for (int j = 0; j < 4; j++) acc[ni][j] = 0.f;

#pragma unroll
        for (int k8 = 0; k8 < 32; k8 += 8) {
            uint32_t ah[4], al[4];
            ah[0] = sm[A_QH + (k8 + c4) * 66 + rb + g];
            ah[1] = sm[A_QH + (k8 + c4) * 66 + rb + g + 8];
            ah[2] = sm[A_QH + (k8 + c4 + 4) * 66 + rb + g];
            ah[3] = sm[A_QH + (k8 + c4 + 4) * 66 + rb + g + 8];
            al[0] = sm[A_QL + (k8 + c4) * 66 + rb + g];
            al[1] = sm[A_QL + (k8 + c4) * 66 + rb + g + 8];
            al[2] = sm[A_QL + (k8 + c4 + 4) * 66 + rb + g];
            al[3] = sm[A_QL + (k8 + c4 + 4) * 66 + rb + g + 8];
#pragma unroll
            for (int ni = 0; ni < 7; ni++) {
                if (ni >= ncnt) break;
                const int cb = (nstart + ni) * 8;
                uint32_t bh[2], bl[2];
                bh[0] = sm[A_KH + (k8 + c4) * 209 + cb + g];
                bh[1] = sm[A_KH + (k8 + c4 + 4) * 209 + cb + g];
                bl[0] = sm[A_KL + (k8 + c4) * 209 + cb + g];
                bl[1] = sm[A_KL + (k8 + c4 + 4) * 209 + cb + g];
                mma8(acc[ni], ah, bh); mma8(acc[ni], ah, bl); mma8(acc[ni], al, bh);
            }
        }
#pragma unroll
        for (int ni = 0; ni < 7; ni++) {
            if (ni >= ncnt) break;
            const int cb = (nstart + ni) * 8;
#pragma unroll
            for (int j = 0; j < 4; j++) {
                const int row = rb + g + ((j >> 1) << 3);
                const int col = cb + c4 * 2 + (j & 1);
                const float m = (col < NPROB && r0 + row < NPOMO)
                              ? Mg[row * NPROB + col] : 0.f;
                Sf[row * 209 + col] = acc[ni][j] * isd + m;
            }
        }
    }
    __syncthreads();

    // ---- phase 2: row softmax; write weights as hi/lo tf32 planes ----
    for (int r = w; r < QROWS; r += 16) {
        float* rowp = Sf + r * 209;
        float vals[7], mx = -INFINITY;
#pragma unroll
        for (int i = 0; i < 7; i++) {
            const int idx = lane + i * 32;
            vals[i] = (idx < NNODE) ? rowp[idx] : -INFINITY;
            mx = fmaxf(mx, vals[i]);
        }
#pragma unroll
        for (int o = 16; o > 0; o >>= 1) mx = fmaxf(mx, __shfl_xor_sync(~0u, mx, o));
        float sum = 0.f;
#pragma unroll
        for (int i = 0; i < 7; i++) {
            const int idx = lane + i * 32;
            vals[i] = (idx < NNODE) ? expf(vals[i] - mx) : 0.f;
            sum += vals[i];
        }
#pragma unroll
        for (int o = 16; o > 0; o >>= 1) sum += __shfl_xor_sync(~0u, sum, o);
        const float inv = 1.f / sum;
#pragma unroll
        for (int i = 0; i < 7; i++) {
            const int idx = lane + i * 32;
            if (idx < 208) {
                const float wv = (idx < NNODE) ? vals[i] * inv : 0.f;
                const uint32_t hi = f2tf(wv);
                sm[A_SH + r * 209 + idx] = hi;
                sm[A_SL + r * 209 + idx] = f2tf(wv - __uint_as_float(hi));
            }
        }
    }
    __syncthreads();

    // ---- phase 3: O = S @ V   (16 jobs: mt = w>>2, nt = w&3) ----
    {
        const int mt = w >> 2, nt = w & 3;
        const int rb = mt * 16, cb = nt * 8;
        float acc[4] = {0.f, 0.f, 0.f, 0.f};
        for (int kt = 0; kt < 26; kt++) {
            const int k8 = kt * 8;
            uint32_t ah[4], al[4], bh[2], bl[2];
            ah[0] = sm[A_SH + (rb + g) * 209 + k8 + c4];
            ah[1] = sm[A_SH + (rb + g + 8) * 209 + k8 + c4];
            ah[2] = sm[A_SH + (rb + g) * 209 + k8 + c4 + 4];
            ah[3] = sm[A_SH + (rb + g + 8) * 209 + k8 + c4 + 4];
            al[0] = sm[A_SL + (rb + g) * 209 + k8 + c4];
            al[1] = sm[A_SL + (rb + g + 8) * 209 + k8 + c4];
            al[2] = sm[A_SL + (rb + g) * 209 + k8 + c4 + 4];
            al[3] = sm[A_SL + (rb + g + 8) * 209 + k8 + c4 + 4];
            bh[0] = sm[A_VH + (k8 + c4) * 33 + cb + g];
            bh[1] = sm[A_VH + (k8 + c4 + 4) * 33 + cb + g];
            bl[0] = sm[A_VL + (k8 + c4) * 33 + cb + g];
            bl[1] = sm[A_VL + (k8 + c4 + 4) * 33 + cb + g];
            mma8(acc, ah, bh); mma8(acc, ah, bl); mma8(acc, al, bh);
        }
#pragma unroll
        for (int j = 0; j < 4; j++) {
            const int row = rb + g + ((j >> 1) << 3), col = cb + c4 * 2 + (j & 1);
            if (r0 + row < NPOMO) Og[(long long)row * NEMB + col] = acc[j];
        }
    }
}

// ---------------- row softmax (final output) ----------------------------------
__global__ void __launch_bounds__(256)
softmax_kernel(float* __restrict__ X, int rows, int L, int stride)
{
    const int r = (blockIdx.x * blockDim.x + threadIdx.x) >> 5;
    const int lane = threadIdx.x & 31;
    if (r >= rows) return;
    float* rowp = X + (long long)r * stride;
    float vals[7], mx = -INFINITY;
#pragma unroll
    for (int i = 0; i < 7; i++) {
        const int idx = lane + i * 32;
        vals[i] = (idx < L) ? rowp[idx] : -INFINITY;
        mx = fmaxf(mx, vals[i]);
    }
#pragma unroll
    for (int o = 16; o > 0; o >>= 1) mx = fmaxf(mx, __shfl_xor_sync(~0u, mx, o));
    float sum = 0.f;
#pragma unroll
    for (int i = 0; i < 7; i++) {
        const int idx = lane + i * 32;
        vals[i] = (idx < L) ? expf(vals[i] - mx) : 0.f;
        sum += vals[i];
    }
#pragma unroll
    for (int o = 16; o > 0; o >>= 1) sum += __shfl_xor_sync(~0u, sum, o);
    const float inv = 1.f / sum;
#pragma unroll
    for (int i = 0; i < 7; i++) {
        const int idx = lane + i * 32;
        if (idx < L) rowp[idx] = vals[i] * inv;
    }
}

static inline int cdiv(int a, int b) { return (a + b - 1) / b; }

extern "C" void kernel_launch(void* const* d_in, const int* in_sizes, int n_in,
                              void* d_out, int out_size)
{
    const float* nodes = (const float*)d_in[0];
    const float* q1    = (const float*)d_in[1];
    const float* lastn = (const float*)d_in[2];
    const float* ninf  = (const float*)d_in[3];
    const float* Wqf   = (const float*)d_in[4];
    const float* Wql   = (const float*)d_in[5];
    const float* Wk    = (const float*)d_in[6];
    const float* Wv    = (const float*)d_in[7];
    const float* Wc    = (const float*)d_in[8];
    const float* bc    = (const float*)d_in[9];
    float* out = (float*)d_out;

    float *kbuf, *vbuf, *qbuf, *obuf, *mhbuf;
    cudaGetSymbolAddress((void**)&kbuf,  g_kbuf);
    cudaGetSymbolAddress((void**)&vbuf,  g_vbuf);
    cudaGetSymbolAddress((void**)&qbuf,  g_qbuf);
    cudaGetSymbolAddress((void**)&obuf,  g_obuf);
    cudaGetSymbolAddress((void**)&mhbuf, g_mhbuf);

    cudaFuncSetAttribute(tf32_gemm, cudaFuncAttributeMaxDynamicSharedMemorySize,
                         GEMM_SMEM_BYTES);
    cudaFuncSetAttribute(attn_kernel, cudaFuncAttributeMaxDynamicSharedMemorySize,
                         ATTN_SMEM_BYTES);

    const dim3 blk(256);
    const float ise = 0.04419417382415922f;    // 1/sqrt(512)
    const int Mn = NB * NNODE, Mq = NB * NPOMO;

    // 1) K = nodes @ Wk
    tf32_gemm<<<dim3(4, cdiv(Mn, 128), 1), blk, GEMM_SMEM_BYTES>>>(
        nodes, Wk, nullptr, nullptr, nullptr, nullptr, kbuf,
        Mn, NEMB, NEMB, NEMB, NEMB, NEMB, 0,0,0,0,0,0,0, 1, 0, 0, 0, 1.f);
    // 2) V = nodes @ Wv
    tf32_gemm<<<dim3(4, cdiv(Mn, 128), 1), blk, GEMM_SMEM_BYTES>>>(
        nodes, Wv, nullptr, nullptr, nullptr, nullptr, vbuf,
        Mn, NEMB, NEMB, NEMB, NEMB, NEMB, 0,0,0,0,0,0,0, 1, 0, 0, 0, 1.f);
    // 3) Q = q1@Wqf + lastn@Wql (dual source)
    tf32_gemm<<<dim3(4, cdiv(Mq, 128), 1), blk, GEMM_SMEM_BYTES>>>(
        q1, Wqf, lastn, Wql, nullptr, nullptr, qbuf,
        Mq, NEMB, NEMB, NEMB, NEMB, NEMB, 0,0,0,0,0,0,0, 1, 0, 0, 0, 1.f);
    // 4) fused attention: scores + mask + softmax + AV -> obuf
    attn_kernel<<<dim3(cdiv(NPOMO, QROWS), NB * NHEAD), dim3(512), ATTN_SMEM_BYTES>>>(
        qbuf, kbuf, vbuf, ninf, obuf);
    // 5) mh = O @ Wc + bc
    tf32_gemm<<<dim3(4, cdiv(Mq, 128), 1), blk, GEMM_SMEM_BYTES>>>(
        obuf, Wc, nullptr, nullptr, bc, nullptr, mhbuf,
        Mq, NEMB, NEMB, NEMB, NEMB, NEMB, 0,0,0,0,0,0,0, 1, 0, 1, 0, 1.f);
    // 6) out = 10*tanh(mh @ nodes[:,:200]^T / sqrt(EMB)) + ninf
    tf32_gemm<<<dim3(cdiv(NPROB, 128), cdiv(NPOMO, 128), NB), blk, GEMM_SMEM_BYTES>>>(
        mhbuf, nodes, nullptr, nullptr, nullptr, ninf, out,
        NPOMO, NPROB, NEMB, NEMB, NEMB, NPROB,
        (long long)NPOMO * NEMB, 0,
        (long long)NNODE * NEMB, 0,
        (long long)NPOMO * NPROB, 0,
        (long long)NPOMO * NPROB,
        1, 1, 2, NPROB, ise);
    // 7) final softmax
    {
        const int rows = NB * NPOMO;
        softmax_kernel<<<cdiv(rows, 8), blk>>>(out, rows, NPROB, NPROB);
    }
}

// round 10
// speedup vs baseline: 1.3875x; 1.0373x over previous
#include <cuda_runtime.h>
#include <math.h>
#include <stdint.h>

#define NB    64
#define NPOMO 200
#define NPROB 200
#define NEMB  512
#define NHEAD 16
#define NHD   32
#define NNODE 201
#define QROWS 48

// ---------------- scratch (device globals) -----------------------------------
static __device__ float g_kbuf[(size_t)NB * NNODE * NEMB];
static __device__ float g_vbuf[(size_t)NB * NNODE * NEMB];
static __device__ float g_qbuf[(size_t)NB * NPOMO * NEMB];
static __device__ float g_obuf[(size_t)NB * NPOMO * NEMB];
static __device__ float g_mhbuf[(size_t)NB * NPOMO * NEMB];

__device__ __forceinline__ uint32_t f2tf(float x) {
    uint32_t r;
    asm("cvt.rna.tf32.f32 %0, %1;" : "=r"(r) : "f"(x));
    return r;
}
__device__ __forceinline__ void mma8(float* c, const uint32_t* a, const uint32_t* b) {
    asm volatile(
        "mma.sync.aligned.m16n8k8.row.col.f32.tf32.tf32.f32 "
        "{%0,%1,%2,%3},{%4,%5,%6,%7},{%8,%9},{%0,%1,%2,%3};"
        : "+f"(c[0]), "+f"(c[1]), "+f"(c[2]), "+f"(c[3])
        : "r"(a[0]), "r"(a[1]), "r"(a[2]), "r"(a[3]), "r"(b[0]), "r"(b[1]));
}
__device__ __forceinline__ float4 ldg4(const float* p, bool ok, int rem) {
    float4 v = make_float4(0.f, 0.f, 0.f, 0.f);
    if (ok && rem > 0) {
        if (rem >= 4) v = *(const float4*)p;
        else { v.x = p[0]; if (rem > 1) v.y = p[1]; if (rem > 2) v.z = p[2]; }
    }
    return v;
}

// ---------------- TF32 GEMM V2: hi/lo in smem, 3-term compute per stage -------
// BM=128, BN=128, BK=16, 256 threads (2x4 warps), double-buffered. (proven R8)
#define SAx(s,tm,k,x) smU[(((s)*2+(tm))*16 + (k))*133 + (x)]
#define SBx(s,tm,k,x) smU[8512 + (((s)*2+(tm))*16 + (k))*133 + (x)]
#define GEMM_SMEM_BYTES (17024 * 4)

__global__ void __launch_bounds__(256)
tf32_gemm(const float* __restrict__ A0, const float* __restrict__ B0,
          const float* __restrict__ A1, const float* __restrict__ B1,
          const float* __restrict__ bias, const float* __restrict__ mask,
          float* __restrict__ C, int M, int N, int K,
          int lda, int ldb, int ldc,
          long long aSb, long long aSh, long long bSb, long long bSh,
          long long cSb, long long cSh, long long mSb,
          int nbH, int transB, int epMode, int maskCols, float alpha)
{
    extern __shared__ uint32_t smU[];

    const int t = threadIdx.x, lane = t & 31, wid = t >> 5;
    const int wm = wid & 1, wn = wid >> 1, g = lane >> 2, c4 = lane & 3;
    const int zb = blockIdx.z / nbH, zh = blockIdx.z - zb * nbH;
    const int m0 = blockIdx.y * 128, n0 = blockIdx.x * 128;

    const long long aOff = (long long)zb * aSb + (long long)zh * aSh;
    const long long bOff = (long long)zb * bSb + (long long)zh * bSh;
    float* Cp = C + (long long)zb * cSb + (long long)zh * cSh;
    const float* Mp = mask ? (mask + (long long)zb * mSb) : nullptr;

    float acc[4][4][4];
#pragma unroll
    for (int mi = 0; mi < 4; mi++)
#pragma unroll
        for (int ni = 0; ni < 4; ni++)
#pragma unroll
            for (int j = 0; j < 4; j++) acc[mi][ni][j] = 0.f;

    const int nkt  = (K + 15) >> 4;
    const int nper = nkt * ((A1 != nullptr) ? 2 : 1);

    float4 va[2], vb[2];
    auto ldregs = [&](int tt) {
        const int src = tt / nkt, k0 = (tt - src * nkt) * 16;
        const float* Ap = (src ? A1 : A0) + aOff;
        const float* Bp = (src ? B1 : B0) + bOff;
#pragma unroll
        for (int i = 0; i < 2; i++) {
            const int f = t + (i << 8), row = f >> 2, kq = (f & 3) << 2;
            va[i] = ldg4(Ap + (long long)(m0 + row) * lda + k0 + kq,
                         (m0 + row) < M, K - (k0 + kq));
        }
#pragma unroll
        for (int i = 0; i < 2; i++) {
            const int f = t + (i << 8);
            if (!transB) {
                const int kr = f >> 5, cq = (f & 31) << 2;
                vb[i] = ldg4(Bp + (long long)(k0 + kr) * ldb + n0 + cq,
                             (k0 + kr) < K, N - (n0 + cq));
            } else {
                const int nr = f >> 2, kq = (f & 3) << 2;
                vb[i] = ldg4(Bp + (long long)(n0 + nr) * ldb + k0 + kq,
                             (n0 + nr) < N, K - (k0 + kq));
            }
        }
    };
    auto stsmem = [&](int s) {
#pragma unroll
        for (int i = 0; i < 2; i++) {
            const int f = t + (i << 8), row = f >> 2, kq = (f & 3) << 2;
            const float e[4] = {va[i].x, va[i].y, va[i].z, va[i].w};
#pragma unroll
            for (int j = 0; j < 4; j++) {
                const uint32_t hi = f2tf(e[j]);
                SAx(s, 0, kq + j, row) = hi;
                SAx(s, 1, kq + j, row) = f2tf(e[j] - __uint_as_float(hi));
            }
        }
#pragma unroll
        for (int i = 0; i < 2; i++) {
            const int f = t + (i << 8);
            const float e[4] = {vb[i].x, vb[i].y, vb[i].z, vb[i].w};
#pragma unroll
            for (int j = 0; j < 4; j++) {
                int kk, cc;
                if (!transB) { kk = f >> 5; cc = ((f & 31) << 2) + j; }
                else         { kk = ((f & 3) << 2) + j; cc = f >> 2; }
                const uint32_t hi = f2tf(e[j]);
                SBx(s, 0, kk, cc) = hi;
                SBx(s, 1, kk, cc) = f2tf(e[j] - __uint_as_float(hi));
            }
        }
    };

    const int rbase = wm * 64 + g, cbase = wn * 32 + c4 * 2;
    auto compute = [&](int s) {
#pragma unroll
        for (int ks = 0; ks < 2; ks++) {
            const int k8 = ks * 8;
            uint32_t bh[4][2], bl[4][2];
#pragma unroll
            for (int ni = 0; ni < 4; ni++) {
                const int cc = wn * 32 + ni * 8 + g;
                bh[ni][0] = SBx(s, 0, k8 + c4, cc);
                bh[ni][1] = SBx(s, 0, k8 + c4 + 4, cc);
                bl[ni][0] = SBx(s, 1, k8 + c4, cc);
                bl[ni][1] = SBx(s, 1, k8 + c4 + 4, cc);
            }
#pragma unroll
            for (int mi = 0; mi < 4; mi++) {
                const int r = rbase + mi * 16;
                uint32_t ah[4], al[4];
                ah[0] = SAx(s, 0, k8 + c4, r);     ah[1] = SAx(s, 0, k8 + c4, r + 8);
                ah[2] = SAx(s, 0, k8 + c4 + 4, r); ah[3] = SAx(s, 0, k8 + c4 + 4, r + 8);
                al[0] = SAx(s, 1, k8 + c4, r);     al[1] = SAx(s, 1, k8 + c4, r + 8);
                al[2] = SAx(s, 1, k8 + c4 + 4, r); al[3] = SAx(s, 1, k8 + c4 + 4, r + 8);
#pragma unroll
                for (int ni = 0; ni < 4; ni++) {
                    mma8(acc[mi][ni], ah, bh[ni]);
                    mma8(acc[mi][ni], ah, bl[ni]);
                    mma8(acc[mi][ni], al, bh[ni]);
                }
            }
        }
    };

    ldregs(0); stsmem(0); __syncthreads();
    for (int tt = 0; tt < nper; tt++) {
        const int cur = tt & 1;
        if (tt + 1 < nper) ldregs(tt + 1);
        compute(cur);
        __syncthreads();
        if (tt + 1 < nper) { stsmem(1 - cur); __syncthreads(); }
    }

#pragma unroll
    for (int mi = 0; mi < 4; mi++)
#pragma unroll
        for (int ni = 0; ni < 4; ni++)
#pragma unroll
            for (int j = 0; j < 4; j++) {
                const int row = m0 + rbase + mi * 16 + ((j >> 1) << 3);
                const int col = n0 + cbase + ni * 8 + (j & 1);
                if (row >= M || col >= N) continue;
                float v = acc[mi][ni][j] * alpha;
                if (epMode == 1) v += bias[col];
                else if (epMode == 2) {
                    v = 10.f * tanhf(v);
                    if (col < maskCols) v += Mp[(long long)row * maskCols + col];
                } else if (epMode == 3) {
                    if (col < maskCols) v += Mp[(long long)row * maskCols + col];
                }
                Cp[(long long)row * ldc + col] = v;
            }
}

// ---------------- fused attention V4: quad-packed fragments (LDS.128) ---------
// Quad(k) = {hi(k), hi(k+4), lo(k), lo(k+4)} -> one LDS.128 per mma fragment.
// u32 offsets:
//   A_K: [kk=16][col 208 pad210] quads -> 13440 u32
//   A_V: [kk=104][col 32 pad34] quads  -> 14144 u32
//   A_Q: [row 48][kk 16 pad20] quads   -> 3840 u32
//   A_S: [row 48][kk 104 pad108] quads -> 20736 u32 (fp32 staged in hi slots)
#define A_K 0
#define A_V 13440
#define A_Q 27584
#define A_S 31424
#define ATTN_SMEM_BYTES (52160 * 4)   // 208640

__global__ void __launch_bounds__(512)
attn_kernel(const float* __restrict__ qbuf, const float* __restrict__ kbuf,
            const float* __restrict__ vbuf, const float* __restrict__ ninf,
            float* __restrict__ obuf)
{
    extern __shared__ uint32_t sm[];
    const int t = threadIdx.x, lane = t & 31, w = t >> 5;
    const int g = lane >> 2, c4 = lane & 3;
    const int z = blockIdx.y, b = z >> 4, h = z & 15;
    const int r0 = blockIdx.x * QROWS;

    const float* Kg = kbuf + ((long long)b * NNODE) * NEMB + h * NHD;
    const float* Vg = vbuf + ((long long)b * NNODE) * NEMB + h * NHD;
    const float* Qg = qbuf + ((long long)b * NPOMO + r0) * NEMB + h * NHD;
    const float* Mg = ninf + ((long long)b * NPOMO + r0) * NPROB;
    float* Og = obuf + ((long long)b * NPOMO + r0) * NEMB + h * NHD;

    // ---- stage K, V quad-packed (pad nodes 201..207 with 0) ----
    for (int i = t; i < 208 * 32; i += 512) {
        const int node = i >> 5, d = i & 31;
        const float kv = (node < NNODE) ? Kg[(long long)node * NEMB + d] : 0.f;
        const float vv = (node < NNODE) ? Vg[(long long)node * NEMB + d] : 0.f;
        const uint32_t kh = f2tf(kv), vh = f2tf(vv);
        const uint32_t kl = f2tf(kv - __uint_as_float(kh));
        const uint32_t vl = f2tf(vv - __uint_as_float(vh));
        // K quad (kk = (d>>3)*4 + (d&3), col = node), word = (d>>2)&1
        const int kq = ((d >> 3) * 4 + (d & 3)) * 210 + node;
        const int kw = (d >> 2) & 1;
        sm[A_K + kq * 4 + kw]     = kh;
        sm[A_K + kq * 4 + 2 + kw] = kl;
        // V quad (kk = (node>>3)*4 + (node&3), col = d), word = (node>>2)&1
        const int vq = ((node >> 3) * 4 + (node & 3)) * 34 + d;
        const int vw = (node >> 2) & 1;
        sm[A_V + vq * 4 + vw]     = vh;
        sm[A_V + vq * 4 + 2 + vw] = vl;
    }
    // ---- stage Q quad-packed (zero rows beyond NPOMO) ----
    for (int i = t; i < QROWS * 32; i += 512) {
        const int row = i >> 5, d = i & 31;
        const float qv = (r0 + row < NPOMO) ? Qg[(long long)row * NEMB + d] : 0.f;
        const uint32_t qh = f2tf(qv);
        const int qq = row * 20 + (d >> 3) * 4 + (d & 3);
        const int qw = (d >> 2) & 1;
        sm[A_Q + qq * 4 + qw]     = qh;
        sm[A_Q + qq * 4 + 2 + qw] = f2tf(qv - __uint_as_float(qh));
    }
    __syncthreads();

    // ---- phase 1: S = Q K^T / sqrt(D) + mask  (3 mt x 26 nt = 78 tiles) ----
    const float isd = 0.17677669529663687f;
    for (int tile = w; tile < 78; tile += 16) {
        const int mt = tile / 26, nt = tile - mt * 26;
        const int rb = mt * 16, cb = nt * 8;
        float ac1[4] = {0.f, 0.f, 0.f, 0.f};
        float ac2[4] = {0.f, 0.f, 0.f, 0.f};
#pragma unroll
        for (int kb = 0; kb < 4; kb++) {
            const uint4 qa = *(const uint4*)&sm[A_Q + ((rb + g) * 20 + kb * 4 + c4) * 4];
            const uint4 qb = *(const uint4*)&sm[A_Q + ((rb + g + 8) * 20 + kb * 4 + c4) * 4];
            const uint4 kq = *(const uint4*)&sm[A_K + ((kb * 4 + c4) * 210 + cb + g) * 4];
            const uint32_t ah[4] = {qa.x, qb.x, qa.y, qb.y};
            const uint32_t al[4] = {qa.z, qb.z, qa.w, qb.w};
            const uint32_t bh[2] = {kq.x, kq.y};
            const uint32_t bl[2] = {kq.z, kq.w};
            mma8(ac1, ah, bh); mma8(ac2, ah, bl); mma8(ac2, al, bh);
        }
#pragma unroll
        for (int j = 0; j < 4; j++) {
            const int row = rb + g + ((j >> 1) << 3);
            const int col = cb + c4 * 2 + (j & 1);
            const float m = (col < NPROB && r0 + row < NPOMO)
                          ? Mg[row * NPROB + col] : 0.f;
            const float v = (ac1[j] + ac2[j]) * isd + m;
            // fp32 staged at packed hi-word position
            sm[A_S + (row * 108 + (col >> 3) * 4 + (col & 3)) * 4 + ((col >> 2) & 1)]
                = __float_as_uint(v);
        }
    }
    __syncthreads();

    // ---- phase 2: row softmax, in-place fp32 -> packed hi/lo tf32 ----
    for (int r = w; r < QROWS; r += 16) {
        int offs[7];
        float vals[7];
        float mx = -INFINITY;
#pragma unroll
        for (int i = 0; i < 7; i++) {
            const int idx = lane + i * 32;
            if (idx < 208) {
                offs[i] = A_S + (r * 108 + (idx >> 3) * 4 + (idx & 3)) * 4 + ((idx >> 2) & 1);
                vals[i] = (idx < NNODE) ? __uint_as_float(sm[offs[i]]) : -INFINITY;
            } else { offs[i] = -1; vals[i] = -INFINITY; }
            mx = fmaxf(mx, vals[i]);
        }
#pragma unroll
        for (int o = 16; o > 0; o >>= 1) mx = fmaxf(mx, __shfl_xor_sync(~0u, mx, o));
        float sum = 0.f;
#pragma unroll
        for (int i = 0; i < 7; i++) {
            const int idx = lane + i * 32;
            vals[i] = (idx < NNODE) ? expf(vals[i] - mx) : 0.f;
            sum += vals[i];
        }
#pragma unroll
        for (int o = 16; o > 0; o >>= 1) sum += __shfl_xor_sync(~0u, sum, o);
        const float inv = 1.f / sum;
#pragma unroll
        for (int i = 0; i < 7; i++) {
            if (offs[i] < 0) continue;
            const float wv = vals[i] * inv;
            const uint32_t hi = f2tf(wv);
            sm[offs[i]]     = hi;
            sm[offs[i] + 2] = f2tf(wv - __uint_as_float(hi));
        }
    }
    __syncthreads();

    // ---- phase 3: O = S @ V  (3 mt x 4 nt = 12 jobs) ----
    if (w < 12) {
        const int mt = w >> 2, nt = w & 3;
        const int rb = mt * 16, cb = nt * 8;
        float ac1[4] = {0.f, 0.f, 0.f, 0.f};
        float ac2[4] = {0.f, 0.f, 0.f, 0.f};
        for (int kt = 0; kt < 26; kt++) {
            const uint4 sa = *(const uint4*)&sm[A_S + ((rb + g) * 108 + kt * 4 + c4) * 4];
            const uint4 sb = *(const uint4*)&sm[A_S + ((rb + g + 8) * 108 + kt * 4 + c4) * 4];
            const uint4 vq = *(const uint4*)&sm[A_V + ((kt * 4 + c4) * 34 + cb + g) * 4];
            const uint32_t ah[4] = {sa.x, sb.x, sa.y, sb.y};
            const uint32_t al[4] = {sa.z, sb.z, sa.w, sb.w};
            const uint32_t bh[2] = {vq.x, vq.y};
            const uint32_t bl[2] = {vq.z, vq.w};
            mma8(ac1, ah, bh); mma8(ac2, ah, bl); mma8(ac2, al, bh);
        }
#pragma unroll
        for (int j = 0; j < 4; j++) {
            const int row = rb + g + ((j >> 1) << 3);
            const int col = cb + c4 * 2 + (j & 1);
            if (r0 + row < NPOMO)
                Og[(long long)row * NEMB + col] = ac1[j] + ac2[j];
        }
    }
}

// ---------------- row softmax (final output) ----------------------------------
__global__ void __launch_bounds__(256)
softmax_kernel(float* __restrict__ X, int rows, int L, int stride)
{
    const int r = (blockIdx.x * blockDim.x + threadIdx.x) >> 5;
    const int lane = threadIdx.x & 31;
    if (r >= rows) return;
    float* rowp = X + (long long)r * stride;
    float vals[7], mx = -INFINITY;
#pragma unroll
    for (int i = 0; i < 7; i++) {
        const int idx = lane + i * 32;
        vals[i] = (idx < L) ? rowp[idx] : -INFINITY;
        mx = fmaxf(mx, vals[i]);
    }
#pragma unroll
    for (int o = 16; o > 0; o >>= 1) mx = fmaxf(mx, __shfl_xor_sync(~0u, mx, o));
    float sum = 0.f;
#pragma unroll
    for (int i = 0; i < 7; i++) {
        const int idx = lane + i * 32;
        vals[i] = (idx < L) ? expf(vals[i] - mx) : 0.f;
        sum += vals[i];
    }
#pragma unroll
    for (int o = 16; o > 0; o >>= 1) sum += __shfl_xor_sync(~0u, sum, o);
    const float inv = 1.f / sum;
#pragma unroll
    for (int i = 0; i < 7; i++) {
        const int idx = lane + i * 32;
        if (idx < L) rowp[idx] = vals[i] * inv;
    }
}

static inline int cdiv(int a, int b) { return (a + b - 1) / b; }

extern "C" void kernel_launch(void* const* d_in, const int* in_sizes, int n_in,
                              void* d_out, int out_size)
{
    const float* nodes = (const float*)d_in[0];
    const float* q1    = (const float*)d_in[1];
    const float* lastn = (const float*)d_in[2];
    const float* ninf  = (const float*)d_in[3];
    const float* Wqf   = (const float*)d_in[4];
    const float* Wql   = (const float*)d_in[5];
    const float* Wk    = (const float*)d_in[6];
    const float* Wv    = (const float*)d_in[7];
    const float* Wc    = (const float*)d_in[8];
    const float* bc    = (const float*)d_in[9];
    float* out = (float*)d_out;

    float *kbuf, *vbuf, *qbuf, *obuf, *mhbuf;
    cudaGetSymbolAddress((void**)&kbuf,  g_kbuf);
    cudaGetSymbolAddress((void**)&vbuf,  g_vbuf);
    cudaGetSymbolAddress((void**)&qbuf,  g_qbuf);
    cudaGetSymbolAddress((void**)&obuf,  g_obuf);
    cudaGetSymbolAddress((void**)&mhbuf, g_mhbuf);

    cudaFuncSetAttribute(tf32_gemm, cudaFuncAttributeMaxDynamicSharedMemorySize,
                         GEMM_SMEM_BYTES);
    cudaFuncSetAttribute(attn_kernel, cudaFuncAttributeMaxDynamicSharedMemorySize,
                         ATTN_SMEM_BYTES);

    const dim3 blk(256);
    const float ise = 0.04419417382415922f;    // 1/sqrt(512)
    const int Mn = NB * NNODE, Mq = NB * NPOMO;

    // 1) K = nodes @ Wk
    tf32_gemm<<<dim3(4, cdiv(Mn, 128), 1), blk, GEMM_SMEM_BYTES>>>(
        nodes, Wk, nullptr, nullptr, nullptr, nullptr, kbuf,
        Mn, NEMB, NEMB, NEMB, NEMB, NEMB, 0,0,0,0,0,0,0, 1, 0, 0, 0, 1.f);
    // 2) V = nodes @ Wv
    tf32_gemm<<<dim3(4, cdiv(Mn, 128), 1), blk, GEMM_SMEM_BYTES>>>(
        nodes, Wv, nullptr, nullptr, nullptr, nullptr, vbuf,
        Mn, NEMB, NEMB, NEMB, NEMB, NEMB, 0,0,0,0,0,0,0, 1, 0, 0, 0, 1.f);
    // 3) Q = q1@Wqf + lastn@Wql (dual source)
    tf32_gemm<<<dim3(4, cdiv(Mq, 128), 1), blk, GEMM_SMEM_BYTES>>>(
        q1, Wqf, lastn, Wql, nullptr, nullptr, qbuf,
        Mq, NEMB, NEMB, NEMB, NEMB, NEMB, 0,0,0,0,0,0,0, 1, 0, 0, 0, 1.f);
    // 4) fused attention: scores + mask + softmax + AV -> obuf
    attn_kernel<<<dim3(cdiv(NPOMO, QROWS), NB * NHEAD), dim3(512), ATTN_SMEM_BYTES>>>(
        qbuf, kbuf, vbuf, ninf, obuf);
    // 5) mh = O @ Wc + bc
    tf32_gemm<<<dim3(4, cdiv(Mq, 128), 1), blk, GEMM_SMEM_BYTES>>>(
        obuf, Wc, nullptr, nullptr, bc, nullptr, mhbuf,
        Mq, NEMB, NEMB, NEMB, NEMB, NEMB, 0,0,0,0,0,0,0, 1, 0, 1, 0, 1.f);
    // 6) out = 10*tanh(mh @ nodes[:,:200]^T / sqrt(EMB)) + ninf
    tf32_gemm<<<dim3(cdiv(NPROB, 128), cdiv(NPOMO, 128), NB), blk, GEMM_SMEM_BYTES>>>(
        mhbuf, nodes, nullptr, nullptr, nullptr, ninf, out,
        NPOMO, NPROB, NEMB, NEMB, NEMB, NPROB,
        (long long)NPOMO * NEMB, 0,
        (long long)NNODE * NEMB, 0,
        (long long)NPOMO * NPROB, 0,
        (long long)NPOMO * NPROB,
        1, 1, 2, NPROB, ise);
    // 7) final softmax
    {
        const int rows = NB * NPOMO;
        softmax_kernel<<<cdiv(rows, 8), blk>>>(out, rows, NPROB, NPROB);
    }
}

// round 13
// speedup vs baseline: 1.3926x; 1.0036x over previous
#include <cuda_runtime.h>
#include <math.h>
#include <stdint.h>

#define NB    64
#define NPOMO 200
#define NPROB 200
#define NEMB  512
#define NHEAD 16
#define NHD   32
#define NNODE 201
#define QROWS 48

// ---------------- scratch (device globals) -----------------------------------
static __device__ float g_kbuf[(size_t)NB * NNODE * NEMB];
static __device__ float g_vbuf[(size_t)NB * NNODE * NEMB];
static __device__ float g_qbuf[(size_t)NB * NPOMO * NEMB];
static __device__ float g_obuf[(size_t)NB * NPOMO * NEMB];
static __device__ float g_mhbuf[(size_t)NB * NPOMO * NEMB];

__device__ __forceinline__ uint32_t f2tf(float x) {
    uint32_t r;
    asm("cvt.rna.tf32.f32 %0, %1;" : "=r"(r) : "f"(x));
    return r;
}
__device__ __forceinline__ void mma8(float* c, const uint32_t* a, const uint32_t* b) {
    asm volatile(
        "mma.sync.aligned.m16n8k8.row.col.f32.tf32.tf32.f32 "
        "{%0,%1,%2,%3},{%4,%5,%6,%7},{%8,%9},{%0,%1,%2,%3};"
        : "+f"(c[0]), "+f"(c[1]), "+f"(c[2]), "+f"(c[3])
        : "r"(a[0]), "r"(a[1]), "r"(a[2]), "r"(a[3]), "r"(b[0]), "r"(b[1]));
}

// ---------------- TF32 GEMM V3: quad smem, BN=64, 3 CTAs/SM -------------------
// BM=128, BN=64, BK=16, 256 thr = 8 warps (4m x 2n), warp tile 32x32.
// Quad = {hi(k), hi(k+4), lo(k), lo(k+4)} : 1 LDS.128 per mma fragment.
// A quads: [s2k = s*2+ks][row 128, stride 129][c4 4]  (pad keeps banks clean)
// B quads: [s2k][cc 64, stride 65][c4 4]
#define QA(s2k,row,c4) (((s2k)*129 + (row))*4 + (c4))
#define QB(s2k,cc,c4)  (2064 + ((s2k)*65 + (cc))*4 + (c4))
#define GEMM_SMEM_BYTES (3104 * 16)   // 49664 B

__global__ void __launch_bounds__(256, 3)
tf32_gemm(const float* __restrict__ A0, const float* __restrict__ B0,
          const float* __restrict__ A1, const float* __restrict__ B1,
          const float* __restrict__ bias, const float* __restrict__ mask,
          float* __restrict__ C, int M, int N, int K,
          int lda, int ldb, int ldc,
          long long aSb, long long aSh, long long bSb, long long bSh,
          long long cSb, long long cSh, long long mSb,
          int nbH, int transB, int epMode, int maskCols, float alpha)
{
    extern __shared__ uint4 smQ[];

    const int t = threadIdx.x, lane = t & 31, wid = t >> 5;
    const int wm = wid & 3, wn = wid >> 2, g = lane >> 2, c4 = lane & 3;
    const int zb = blockIdx.z / nbH, zh = blockIdx.z - zb * nbH;
    const int m0 = blockIdx.y * 128, n0 = blockIdx.x * 64;

    const long long aOff = (long long)zb * aSb + (long long)zh * aSh;
    const long long bOff = (long long)zb * bSb + (long long)zh * bSh;
    float* Cp = C + (long long)zb * cSb + (long long)zh * cSh;
    const float* Mp = mask ? (mask + (long long)zb * mSb) : nullptr;

    float acc[2][4][4];
#pragma unroll
    for (int mi = 0; mi < 2; mi++)
#pragma unroll
        for (int ni = 0; ni < 4; ni++)
#pragma unroll
            for (int j = 0; j < 4; j++) acc[mi][ni][j] = 0.f;

    const int nkt  = (K + 15) >> 4;
    const int nper = nkt * ((A1 != nullptr) ? 2 : 1);

    // staging registers: element pairs (k, k+4)
    float a0[4], a1v[4], b0[2], b1v[2];

    auto ldregs = [&](int tt) {
        const int src = tt / nkt, k0 = (tt - src * nkt) * 16;
        const float* Ap = (src ? A1 : A0) + aOff;
        const float* Bp = (src ? B1 : B0) + bOff;
#pragma unroll
        for (int i = 0; i < 4; i++) {
            const int f = t + (i << 8);
            const int fc4 = f & 3, fks = (f >> 2) & 1, row = f >> 3;
            const int k = k0 + fks * 8 + fc4;
            const bool rok = (m0 + row) < M;
            a0[i]  = (rok && k     < K) ? Ap[(long long)(m0 + row) * lda + k]     : 0.f;
            a1v[i] = (rok && k + 4 < K) ? Ap[(long long)(m0 + row) * lda + k + 4] : 0.f;
        }
#pragma unroll
        for (int i = 0; i < 2; i++) {
            const int f = t + (i << 8);
            const int fc4 = f & 3, fks = (f >> 2) & 1, cc = f >> 3;
            const int k = k0 + fks * 8 + fc4;
            const bool cok = (n0 + cc) < N;
            if (!transB) {
                b0[i]  = (cok && k     < K) ? Bp[(long long)k * ldb + n0 + cc]       : 0.f;
                b1v[i] = (cok && k + 4 < K) ? Bp[(long long)(k + 4) * ldb + n0 + cc] : 0.f;
            } else {
                b0[i]  = (cok && k     < K) ? Bp[(long long)(n0 + cc) * ldb + k]     : 0.f;
                b1v[i] = (cok && k + 4 < K) ? Bp[(long long)(n0 + cc) * ldb + k + 4] : 0.f;
            }
        }
    };
    auto stq = [&](int s) {
#pragma unroll
        for (int i = 0; i < 4; i++) {
            const int f = t + (i << 8);
            const int fc4 = f & 3, fks = (f >> 2) & 1, row = f >> 3;
            const uint32_t h0 = f2tf(a0[i]), h1 = f2tf(a1v[i]);
            uint4 q;
            q.x = h0; q.y = h1;
            q.z = f2tf(a0[i]  - __uint_as_float(h0));
            q.w = f2tf(a1v[i] - __uint_as_float(h1));
            smQ[QA(s * 2 + fks, row, fc4)] = q;
        }
#pragma unroll
        for (int i = 0; i < 2; i++) {
            const int f = t + (i << 8);
            const int fc4 = f & 3, fks = (f >> 2) & 1, cc = f >> 3;
            const uint32_t h0 = f2tf(b0[i]), h1 = f2tf(b1v[i]);
            uint4 q;
            q.x = h0; q.y = h1;
            q.z = f2tf(b0[i]  - __uint_as_float(h0));
            q.w = f2tf(b1v[i] - __uint_as_float(h1));
            smQ[QB(s * 2 + fks, cc, fc4)] = q;
        }
    };

    auto compute = [&](int s) {
#pragma unroll
        for (int ks = 0; ks < 2; ks++) {
            const int s2k = s * 2 + ks;
            uint4 bq[4];
#pragma unroll
            for (int ni = 0; ni < 4; ni++)
                bq[ni] = smQ[QB(s2k, wn * 32 + ni * 8 + g, c4)];
#pragma unroll
            for (int mi = 0; mi < 2; mi++) {
                const int r = wm * 32 + mi * 16 + g;
                const uint4 qa = smQ[QA(s2k, r, c4)];
                const uint4 qb2 = smQ[QA(s2k, r + 8, c4)];
                const uint32_t ah[4] = {qa.x, qb2.x, qa.y, qb2.y};
                const uint32_t al[4] = {qa.z, qb2.z, qa.w, qb2.w};
#pragma unroll
                for (int ni = 0; ni < 4; ni++) {
                    const uint32_t bh[2] = {bq[ni].x, bq[ni].y};
                    const uint32_t bl[2] = {bq[ni].z, bq[ni].w};
                    mma8(acc[mi][ni], ah, bh);
                    mma8(acc[mi][ni], ah, bl);
                    mma8(acc[mi][ni], al, bh);
                }
            }
        }
    };

    ldregs(0); stq(0); __syncthreads();
    for (int tt = 0; tt < nper; tt++) {
        const int cur = tt & 1;
        if (tt + 1 < nper) ldregs(tt + 1);
        compute(cur);
        if (tt + 1 < nper) stq(1 - cur);   // other buffer: safe (read 2 stages ago)
        __syncthreads();
    }

    // ---- epilogue ----
#pragma unroll
    for (int mi = 0; mi < 2; mi++)
#pragma unroll
        for (int ni = 0; ni < 4; ni++)
#pragma unroll
            for (int j = 0; j < 4; j++) {
                const int row = m0 + wm * 32 + mi * 16 + g + ((j >> 1) << 3);
                const int col = n0 + wn * 32 + ni * 8 + c4 * 2 + (j & 1);
                if (row >= M || col >= N) continue;
                float v = acc[mi][ni][j] * alpha;
                if (epMode == 1) v += bias[col];
                else if (epMode == 2) {
                    v = 10.f * tanhf(v);
                    if (col < maskCols) v += Mp[(long long)row * maskCols + col];
                } else if (epMode == 3) {
                    if (col < maskCols) v += Mp[(long long)row * maskCols + col];
                }
                Cp[(long long)row * ldc + col] = v;
            }
}

// ---------------- fused attention V5: K/V staged once, q-tile loop ------------
// One block per (b*16+h); loops 5 q-tiles of 48 rows. Quad-packed smem (R10).
#define A_K 0
#define A_V 13440
#define A_Q 27584
#define A_S 31424
#define ATTN_SMEM_BYTES (52160 * 4)   // 208640

__global__ void __launch_bounds__(512)
attn_kernel(const float* __restrict__ qbuf, const float* __restrict__ kbuf,
            const float* __restrict__ vbuf, const float* __restrict__ ninf,
            float* __restrict__ obuf)
{
    extern __shared__ uint32_t sm[];
    const int t = threadIdx.x, lane = t & 31, w = t >> 5;
    const int g = lane >> 2, c4 = lane & 3;
    const int z = blockIdx.x, b = z >> 4, h = z & 15;

    const float* Kg = kbuf + ((long long)b * NNODE) * NEMB + h * NHD;
    const float* Vg = vbuf + ((long long)b * NNODE) * NEMB + h * NHD;

    // ---- stage K, V quad-packed ONCE (pad nodes 201..207 with 0) ----
    for (int i = t; i < 208 * 32; i += 512) {
        const int node = i >> 5, d = i & 31;
        const float kv = (node < NNODE) ? Kg[(long long)node * NEMB + d] : 0.f;
        const float vv = (node < NNODE) ? Vg[(long long)node * NEMB + d] : 0.f;
        const uint32_t kh = f2tf(kv), vh = f2tf(vv);
        const uint32_t kl = f2tf(kv - __uint_as_float(kh));
        const uint32_t vl = f2tf(vv - __uint_as_float(vh));
        const int kq = ((d >> 3) * 4 + (d & 3)) * 210 + node;
        const int kw = (d >> 2) & 1;
        sm[A_K + kq * 4 + kw]     = kh;
        sm[A_K + kq * 4 + 2 + kw] = kl;
        const int vq = ((node >> 3) * 4 + (node & 3)) * 34 + d;
        const int vw = (node >> 2) & 1;
        sm[A_V + vq * 4 + vw]     = vh;
        sm[A_V + vq * 4 + 2 + vw] = vl;
    }
    __syncthreads();

    const float isd = 0.17677669529663687f;

    for (int r0 = 0; r0 < NPOMO; r0 += QROWS) {
        const float* Qg = qbuf + ((long long)b * NPOMO + r0) * NEMB + h * NHD;
        const float* Mg = ninf + ((long long)b * NPOMO + r0) * NPROB;
        float* Og = obuf + ((long long)b * NPOMO + r0) * NEMB + h * NHD;

        // ---- stage Q quad-packed (zero rows beyond NPOMO) ----
        for (int i = t; i < QROWS * 32; i += 512) {
            const int row = i >> 5, d = i & 31;
            const float qv = (r0 + row < NPOMO) ? Qg[(long long)row * NEMB + d] : 0.f;
            const uint32_t qh = f2tf(qv);
            const int qq = row * 20 + (d >> 3) * 4 + (d & 3);
            const int qw = (d >> 2) & 1;
            sm[A_Q + qq * 4 + qw]     = qh;
            sm[A_Q + qq * 4 + 2 + qw] = f2tf(qv - __uint_as_float(qh));
        }
        __syncthreads();

        // ---- phase 1: S = Q K^T / sqrt(D) + mask (3 mt x 26 nt) ----
        for (int tile = w; tile < 78; tile += 16) {
            const int mt = tile / 26, nt = tile - mt * 26;
            const int rb = mt * 16, cb = nt * 8;
            float ac1[4] = {0.f, 0.f, 0.f, 0.f};
            float ac2[4] = {0.f, 0.f, 0.f, 0.f};
#pragma unroll
            for (int kb = 0; kb < 4; kb++) {
                const uint4 qa = *(const uint4*)&sm[A_Q + ((rb + g) * 20 + kb * 4 + c4) * 4];
                const uint4 qb = *(const uint4*)&sm[A_Q + ((rb + g + 8) * 20 + kb * 4 + c4) * 4];
                const uint4 kq = *(const uint4*)&sm[A_K + ((kb * 4 + c4) * 210 + cb + g) * 4];
                const uint32_t ah[4] = {qa.x, qb.x, qa.y, qb.y};
                const uint32_t al[4] = {qa.z, qb.z, qa.w, qb.w};
                const uint32_t bh[2] = {kq.x, kq.y};
                const uint32_t bl[2] = {kq.z, kq.w};
                mma8(ac1, ah, bh); mma8(ac2, ah, bl); mma8(ac2, al, bh);
            }
#pragma unroll
            for (int j = 0; j < 4; j++) {
                const int row = rb + g + ((j >> 1) << 3);
                const int col = cb + c4 * 2 + (j & 1);
                const float m = (col < NPROB && r0 + row < NPOMO)
                              ? Mg[row * NPROB + col] : 0.f;
                const float v = (ac1[j] + ac2[j]) * isd + m;
                sm[A_S + (row * 108 + (col >> 3) * 4 + (col & 3)) * 4 + ((col >> 2) & 1)]
                    = __float_as_uint(v);
            }
        }
        __syncthreads();

        // ---- phase 2: row softmax, in-place fp32 -> packed hi/lo tf32 ----
        for (int r = w; r < QROWS; r += 16) {
            int offs[7];
            float vals[7];
            float mx = -INFINITY;
#pragma unroll
            for (int i = 0; i < 7; i++) {
                const int idx = lane + i * 32;
                if (idx < 208) {
                    offs[i] = A_S + (r * 108 + (idx >> 3) * 4 + (idx & 3)) * 4 + ((idx >> 2) & 1);
                    vals[i] = (idx < NNODE) ? __uint_as_float(sm[offs[i]]) : -INFINITY;
                } else { offs[i] = -1; vals[i] = -INFINITY; }
                mx = fmaxf(mx, vals[i]);
            }
#pragma unroll
            for (int o = 16; o > 0; o >>= 1) mx = fmaxf(mx, __shfl_xor_sync(~0u, mx, o));
            float sum = 0.f;
#pragma unroll
            for (int i = 0; i < 7; i++) {
                const int idx = lane + i * 32;
                vals[i] = (idx < NNODE) ? expf(vals[i] - mx) : 0.f;
                sum += vals[i];
            }
#pragma unroll
            for (int o = 16; o > 0; o >>= 1) sum += __shfl_xor_sync(~0u, sum, o);
            const float inv = 1.f / sum;
#pragma unroll
            for (int i = 0; i < 7; i++) {
                if (offs[i] < 0) continue;
                const float wv = vals[i] * inv;
                const uint32_t hi = f2tf(wv);
                sm[offs[i]]     = hi;
                sm[offs[i] + 2] = f2tf(wv - __uint_as_float(hi));
            }
        }
        __syncthreads();

        // ---- phase 3: O = S @ V (3 mt x 4 nt = 12 jobs) ----
        if (w < 12) {
            const int mt = w >> 2, nt = w & 3;
            const int rb = mt * 16, cb = nt * 8;
            float ac1[4] = {0.f, 0.f, 0.f, 0.f};
            float ac2[4] = {0.f, 0.f, 0.f, 0.f};
            for (int kt = 0; kt < 26; kt++) {
                const uint4 sa = *(const uint4*)&sm[A_S + ((rb + g) * 108 + kt * 4 + c4) * 4];
                const uint4 sb = *(const uint4*)&sm[A_S + ((rb + g + 8) * 108 + kt * 4 + c4) * 4];
                const uint4 vq = *(const uint4*)&sm[A_V + ((kt * 4 + c4) * 34 + cb + g) * 4];
                const uint32_t ah[4] = {sa.x, sb.x, sa.y, sb.y};
                const uint32_t al[4] = {sa.z, sb.z, sa.w, sb.w};
                const uint32_t bh[2] = {vq.x, vq.y};
                const uint32_t bl[2] = {vq.z, vq.w};
                mma8(ac1, ah, bh); mma8(ac2, ah, bl); mma8(ac2, al, bh);
            }
#pragma unroll
            for (int j = 0; j < 4; j++) {
                const int row = rb + g + ((j >> 1) << 3);
                const int col = cb + c4 * 2 + (j & 1);
                if (r0 + row < NPOMO)
                    Og[(long long)row * NEMB + col] = ac1[j] + ac2[j];
            }
        }
        __syncthreads();
    }
}

// ---------------- row softmax (final output) ----------------------------------
__global__ void __launch_bounds__(256)
softmax_kernel(float* __restrict__ X, int rows, int L, int stride)
{
    const int r = (blockIdx.x * blockDim.x + threadIdx.x) >> 5;
    const int lane = threadIdx.x & 31;
    if (r >= rows) return;
    float* rowp = X + (long long)r * stride;
    float vals[7], mx = -INFINITY;
#pragma unroll
    for (int i = 0; i < 7; i++) {
        const int idx = lane + i * 32;
        vals[i] = (idx < L) ? rowp[idx] : -INFINITY;
        mx = fmaxf(mx, vals[i]);
    }
#pragma unroll
    for (int o = 16; o > 0; o >>= 1) mx = fmaxf(mx, __shfl_xor_sync(~0u, mx, o));
    float sum = 0.f;
#pragma unroll
    for (int i = 0; i < 7; i++) {
        const int idx = lane + i * 32;
        vals[i] = (idx < L) ? expf(vals[i] - mx) : 0.f;
        sum += vals[i];
    }
#pragma unroll
    for (int o = 16; o > 0; o >>= 1) sum += __shfl_xor_sync(~0u, sum, o);
    const float inv = 1.f / sum;
#pragma unroll
    for (int i = 0; i < 7; i++) {
        const int idx = lane + i * 32;
        if (idx < L) rowp[idx] = vals[i] * inv;
    }
}

static inline int cdiv(int a, int b) { return (a + b - 1) / b; }

extern "C" void kernel_launch(void* const* d_in, const int* in_sizes, int n_in,
                              void* d_out, int out_size)
{
    const float* nodes = (const float*)d_in[0];
    const float* q1    = (const float*)d_in[1];
    const float* lastn = (const float*)d_in[2];
    const float* ninf  = (const float*)d_in[3];
    const float* Wqf   = (const float*)d_in[4];
    const float* Wql   = (const float*)d_in[5];
    const float* Wk    = (const float*)d_in[6];
    const float* Wv    = (const float*)d_in[7];
    const float* Wc    = (const float*)d_in[8];
    const float* bc    = (const float*)d_in[9];
    float* out = (float*)d_out;

    float *kbuf, *vbuf, *qbuf, *obuf, *mhbuf;
    cudaGetSymbolAddress((void**)&kbuf,  g_kbuf);
    cudaGetSymbolAddress((void**)&vbuf,  g_vbuf);
    cudaGetSymbolAddress((void**)&qbuf,  g_qbuf);
    cudaGetSymbolAddress((void**)&obuf,  g_obuf);
    cudaGetSymbolAddress((void**)&mhbuf, g_mhbuf);

    cudaFuncSetAttribute(tf32_gemm, cudaFuncAttributeMaxDynamicSharedMemorySize,
                         GEMM_SMEM_BYTES);
    cudaFuncSetAttribute(attn_kernel, cudaFuncAttributeMaxDynamicSharedMemorySize,
                         ATTN_SMEM_BYTES);

    const dim3 blk(256);
    const float ise = 0.04419417382415922f;    // 1/sqrt(512)
    const int Mn = NB * NNODE, Mq = NB * NPOMO;

    // 1) K = nodes @ Wk
    tf32_gemm<<<dim3(8, cdiv(Mn, 128), 1), blk, GEMM_SMEM_BYTES>>>(
        nodes, Wk, nullptr, nullptr, nullptr, nullptr, kbuf,
        Mn, NEMB, NEMB, NEMB, NEMB, NEMB, 0,0,0,0,0,0,0, 1, 0, 0, 0, 1.f);
    // 2) V = nodes @ Wv
    tf32_gemm<<<dim3(8, cdiv(Mn, 128), 1), blk, GEMM_SMEM_BYTES>>>(
        nodes, Wv, nullptr, nullptr, nullptr, nullptr, vbuf,
        Mn, NEMB, NEMB, NEMB, NEMB, NEMB, 0,0,0,0,0,0,0, 1, 0, 0, 0, 1.f);
    // 3) Q = q1@Wqf + lastn@Wql (dual source)
    tf32_gemm<<<dim3(8, cdiv(Mq, 128), 1), blk, GEMM_SMEM_BYTES>>>(
        q1, Wqf, lastn, Wql, nullptr, nullptr, qbuf,
        Mq, NEMB, NEMB, NEMB, NEMB, NEMB, 0,0,0,0,0,0,0, 1, 0, 0, 0, 1.f);
    // 4) fused attention: scores + mask + softmax + AV -> obuf
    attn_kernel<<<dim3(NB * NHEAD), dim3(512), ATTN_SMEM_BYTES>>>(
        qbuf, kbuf, vbuf, ninf, obuf);
    // 5) mh = O @ Wc + bc
    tf32_gemm<<<dim3(8, cdiv(Mq, 128), 1), blk, GEMM_SMEM_BYTES>>>(
        obuf, Wc, nullptr, nullptr, bc, nullptr, mhbuf,
        Mq, NEMB, NEMB, NEMB, NEMB, NEMB, 0,0,0,0,0,0,0, 1, 0, 1, 0, 1.f);
    // 6) out = 10*tanh(mh @ nodes[:,:200]^T / sqrt(EMB)) + ninf
    tf32_gemm<<<dim3(cdiv(NPROB, 64), cdiv(NPOMO, 128), NB), blk, GEMM_SMEM_BYTES>>>(
        mhbuf, nodes, nullptr, nullptr, nullptr, ninf, out,
        NPOMO, NPROB, NEMB, NEMB, NEMB, NPROB,
        (long long)NPOMO * NEMB, 0,
        (long long)NNODE * NEMB, 0,
        (long long)NPOMO * NPROB, 0,
        (long long)NPOMO * NPROB,
        1, 1, 2, NPROB, ise);
    // 7) final softmax
    {
        const int rows = NB * NPOMO;
        softmax_kernel<<<cdiv(rows, 8), blk>>>(out, rows, NPROB, NPROB);
    }
}

// round 17
// speedup vs baseline: 1.8079x; 1.2983x over previous
#include <cuda_runtime.h>
#include <math.h>
#include <stdint.h>

#define NB    64
#define NPOMO 200
#define NPROB 200
#define NEMB  512
#define NHEAD 16
#define NHD   32
#define NNODE 201
#define QROWS 48

// ---------------- scratch (device globals) -----------------------------------
static __device__ float g_kbuf[(size_t)NB * NNODE * NEMB];
static __device__ float g_vbuf[(size_t)NB * NNODE * NEMB];
static __device__ float g_qbuf[(size_t)NB * NPOMO * NEMB];
static __device__ float g_obuf[(size_t)NB * NPOMO * NEMB];
static __device__ float g_mhbuf[(size_t)NB * NPOMO * NEMB];

__device__ __forceinline__ uint32_t f2tf(float x) {
    uint32_t r;
    asm("cvt.rna.tf32.f32 %0, %1;" : "=r"(r) : "f"(x));
    return r;
}
__device__ __forceinline__ void mma8(float* c, const uint32_t* a, const uint32_t* b) {
    asm volatile(
        "mma.sync.aligned.m16n8k8.row.col.f32.tf32.tf32.f32 "
        "{%0,%1,%2,%3},{%4,%5,%6,%7},{%8,%9},{%0,%1,%2,%3};"
        : "+f"(c[0]), "+f"(c[1]), "+f"(c[2]), "+f"(c[3])
        : "r"(a[0]), "r"(a[1]), "r"(a[2]), "r"(a[3]), "r"(b[0]), "r"(b[1]));
}

// ---------------- TF32 GEMM V4: V2 tiling + quad smem + 1 barrier/stage -------
// BM=128, BN=128, BK=16, 256 thr = 8 warps (2m x 4n), warp tile 64x32.
// Quad = {hi(k), hi(k+4), lo(k), lo(k+4)} : 1 LDS.128 per mma fragment.
// A quads: [s2k = s*2+ks][row 128][c4 4] ; B quads: [s2k][cc 128][c4 4]
#define QA(s2k,row,c4) (((s2k)*128 + (row))*4 + (c4))
#define QB(s2k,cc,c4)  (2048 + ((s2k)*128 + (cc))*4 + (c4))
#define GEMM_SMEM_BYTES (4096 * 16)   // 65536 B

__global__ void __launch_bounds__(256)
tf32_gemm(const float* __restrict__ A0, const float* __restrict__ B0,
          const float* __restrict__ A1, const float* __restrict__ B1,
          const float* __restrict__ bias, const float* __restrict__ mask,
          float* __restrict__ C, int M, int N, int K,
          int lda, int ldb, int ldc,
          long long aSb, long long aSh, long long bSb, long long bSh,
          long long cSb, long long cSh, long long mSb,
          int nbH, int transB, int epMode, int maskCols, float alpha)
{
    extern __shared__ uint4 smQ[];

    const int t = threadIdx.x, lane = t & 31, wid = t >> 5;
    const int wm = wid & 1, wn = wid >> 1, g = lane >> 2, c4 = lane & 3;
    const int zb = blockIdx.z / nbH, zh = blockIdx.z - zb * nbH;
    const int m0 = blockIdx.y * 128, n0 = blockIdx.x * 128;

    const long long aOff = (long long)zb * aSb + (long long)zh * aSh;
    const long long bOff = (long long)zb * bSb + (long long)zh * bSh;
    float* Cp = C + (long long)zb * cSb + (long long)zh * cSh;
    const float* Mp = mask ? (mask + (long long)zb * mSb) : nullptr;

    float acc[4][4][4];
#pragma unroll
    for (int mi = 0; mi < 4; mi++)
#pragma unroll
        for (int ni = 0; ni < 4; ni++)
#pragma unroll
            for (int j = 0; j < 4; j++) acc[mi][ni][j] = 0.f;

    const int nkt  = (K + 15) >> 4;
    const int nper = nkt * ((A1 != nullptr) ? 2 : 1);

    // staging registers: element pairs (k, k+4), 4 quads A + 4 quads B
    float a0[4], a1v[4], b0[4], b1v[4];

    auto ldregs = [&](int tt) {
        const int src = tt / nkt, k0 = (tt - src * nkt) * 16;
        const float* Ap = (src ? A1 : A0) + aOff;
        const float* Bp = (src ? B1 : B0) + bOff;
#pragma unroll
        for (int i = 0; i < 4; i++) {
            const int f = t + (i << 8);
            const int fc4 = f & 3, fks = (f >> 2) & 1, row = f >> 3;
            const int k = k0 + fks * 8 + fc4;
            const bool rok = (m0 + row) < M;
            a0[i]  = (rok && k     < K) ? Ap[(long long)(m0 + row) * lda + k]     : 0.f;
            a1v[i] = (rok && k + 4 < K) ? Ap[(long long)(m0 + row) * lda + k + 4] : 0.f;
        }
#pragma unroll
        for (int i = 0; i < 4; i++) {
            const int f = t + (i << 8);
            const int fc4 = f & 3, fks = (f >> 2) & 1, cc = f >> 3;
            const int k = k0 + fks * 8 + fc4;
            const bool cok = (n0 + cc) < N;
            if (!transB) {
                b0[i]  = (cok && k     < K) ? Bp[(long long)k * ldb + n0 + cc]       : 0.f;
                b1v[i] = (cok && k + 4 < K) ? Bp[(long long)(k + 4) * ldb + n0 + cc] : 0.f;
            } else {
                b0[i]  = (cok && k     < K) ? Bp[(long long)(n0 + cc) * ldb + k]     : 0.f;
                b1v[i] = (cok && k + 4 < K) ? Bp[(long long)(n0 + cc) * ldb + k + 4] : 0.f;
            }
        }
    };
    auto stq = [&](int s) {
#pragma unroll
        for (int i = 0; i < 4; i++) {
            const int f = t + (i << 8);
            const int fc4 = f & 3, fks = (f >> 2) & 1, row = f >> 3;
            const uint32_t h0 = f2tf(a0[i]), h1 = f2tf(a1v[i]);
            uint4 q;
            q.x = h0; q.y = h1;
            q.z = f2tf(a0[i]  - __uint_as_float(h0));
            q.w = f2tf(a1v[i] - __uint_as_float(h1));
            smQ[QA(s * 2 + fks, row, fc4)] = q;
        }
#pragma unroll
        for (int i = 0; i < 4; i++) {
            const int f = t + (i << 8);
            const int fc4 = f & 3, fks = (f >> 2) & 1, cc = f >> 3;
            const uint32_t h0 = f2tf(b0[i]), h1 = f2tf(b1v[i]);
            uint4 q;
            q.x = h0; q.y = h1;
            q.z = f2tf(b0[i]  - __uint_as_float(h0));
            q.w = f2tf(b1v[i] - __uint_as_float(h1));
            smQ[QB(s * 2 + fks, cc, fc4)] = q;
        }
    };

    auto compute = [&](int s) {
#pragma unroll
        for (int ks = 0; ks < 2; ks++) {
            const int s2k = s * 2 + ks;
            uint4 bq[4];
#pragma unroll
            for (int ni = 0; ni < 4; ni++)
                bq[ni] = smQ[QB(s2k, wn * 32 + ni * 8 + g, c4)];
#pragma unroll
            for (int mi = 0; mi < 4; mi++) {
                const int r = wm * 64 + mi * 16 + g;
                const uint4 qa  = smQ[QA(s2k, r, c4)];
                const uint4 qb2 = smQ[QA(s2k, r + 8, c4)];
                const uint32_t ah[4] = {qa.x, qb2.x, qa.y, qb2.y};
                const uint32_t al[4] = {qa.z, qb2.z, qa.w, qb2.w};
#pragma unroll
                for (int ni = 0; ni < 4; ni++) {
                    const uint32_t bh[2] = {bq[ni].x, bq[ni].y};
                    const uint32_t bl[2] = {bq[ni].z, bq[ni].w};
                    mma8(acc[mi][ni], ah, bh);
                    mma8(acc[mi][ni], ah, bl);
                    mma8(acc[mi][ni], al, bh);
                }
            }
        }
    };

    ldregs(0); stq(0); __syncthreads();
    for (int tt = 0; tt < nper; tt++) {
        const int cur = tt & 1;
        if (tt + 1 < nper) ldregs(tt + 1);
        compute(cur);
        if (tt + 1 < nper) stq(1 - cur);   // other buffer: last read 2 stages ago
        __syncthreads();
    }

    // ---- epilogue ----
#pragma unroll
    for (int mi = 0; mi < 4; mi++)
#pragma unroll
        for (int ni = 0; ni < 4; ni++)
#pragma unroll
            for (int j = 0; j < 4; j++) {
                const int row = m0 + wm * 64 + mi * 16 + g + ((j >> 1) << 3);
                const int col = n0 + wn * 32 + ni * 8 + c4 * 2 + (j & 1);
                if (row >= M || col >= N) continue;
                float v = acc[mi][ni][j] * alpha;
                if (epMode == 1) v += bias[col];
                else if (epMode == 2) {
                    v = 10.f * tanhf(v);
                    if (col < maskCols) v += Mp[(long long)row * maskCols + col];
                } else if (epMode == 3) {
                    if (col < maskCols) v += Mp[(long long)row * maskCols + col];
                }
                Cp[(long long)row * ldc + col] = v;
            }
}

// ---------------- fused attention V5 (unchanged from R13: 405us, proven) ------
#define A_K 0
#define A_V 13440
#define A_Q 27584
#define A_S 31424
#define ATTN_SMEM_BYTES (52160 * 4)   // 208640

__global__ void __launch_bounds__(512)
attn_kernel(const float* __restrict__ qbuf, const float* __restrict__ kbuf,
            const float* __restrict__ vbuf, const float* __restrict__ ninf,
            float* __restrict__ obuf)
{
    extern __shared__ uint32_t sm[];
    const int t = threadIdx.x, lane = t & 31, w = t >> 5;
    const int g = lane >> 2, c4 = lane & 3;
    const int z = blockIdx.x, b = z >> 4, h = z & 15;

    const float* Kg = kbuf + ((long long)b * NNODE) * NEMB + h * NHD;
    const float* Vg = vbuf + ((long long)b * NNODE) * NEMB + h * NHD;

    for (int i = t; i < 208 * 32; i += 512) {
        const int node = i >> 5, d = i & 31;
        const float kv = (node < NNODE) ? Kg[(long long)node * NEMB + d] : 0.f;
        const float vv = (node < NNODE) ? Vg[(long long)node * NEMB + d] : 0.f;
        const uint32_t kh = f2tf(kv), vh = f2tf(vv);
        const uint32_t kl = f2tf(kv - __uint_as_float(kh));
        const uint32_t vl = f2tf(vv - __uint_as_float(vh));
        const int kq = ((d >> 3) * 4 + (d & 3)) * 210 + node;
        const int kw = (d >> 2) & 1;
        sm[A_K + kq * 4 + kw]     = kh;
        sm[A_K + kq * 4 + 2 + kw] = kl;
        const int vq = ((node >> 3) * 4 + (node & 3)) * 34 + d;
        const int vw = (node >> 2) & 1;
        sm[A_V + vq * 4 + vw]     = vh;
        sm[A_V + vq * 4 + 2 + vw] = vl;
    }
    __syncthreads();

    const float isd = 0.17677669529663687f;

    for (int r0 = 0; r0 < NPOMO; r0 += QROWS) {
        const float* Qg = qbuf + ((long long)b * NPOMO + r0) * NEMB + h * NHD;
        const float* Mg = ninf + ((long long)b * NPOMO + r0) * NPROB;
        float* Og = obuf + ((long long)b * NPOMO + r0) * NEMB + h * NHD;

        for (int i = t; i < QROWS * 32; i += 512) {
            const int row = i >> 5, d = i & 31;
            const float qv = (r0 + row < NPOMO) ? Qg[(long long)row * NEMB + d] : 0.f;
            const uint32_t qh = f2tf(qv);
            const int qq = row * 20 + (d >> 3) * 4 + (d & 3);
            const int qw = (d >> 2) & 1;
            sm[A_Q + qq * 4 + qw]     = qh;
            sm[A_Q + qq * 4 + 2 + qw] = f2tf(qv - __uint_as_float(qh));
        }
        __syncthreads();

        for (int tile = w; tile < 78; tile += 16) {
            const int mt = tile / 26, nt = tile - mt * 26;
            const int rb = mt * 16, cb = nt * 8;
            float ac1[4] = {0.f, 0.f, 0.f, 0.f};
            float ac2[4] = {0.f, 0.f, 0.f, 0.f};
#pragma unroll
            for (int kb = 0; kb < 4; kb++) {
                const uint4 qa = *(const uint4*)&sm[A_Q + ((rb + g) * 20 + kb * 4 + c4) * 4];
                const uint4 qb = *(const uint4*)&sm[A_Q + ((rb + g + 8) * 20 + kb * 4 + c4) * 4];
                const uint4 kq = *(const uint4*)&sm[A_K + ((kb * 4 + c4) * 210 + cb + g) * 4];
                const uint32_t ah[4] = {qa.x, qb.x, qa.y, qb.y};
                const uint32_t al[4] = {qa.z, qb.z, qa.w, qb.w};
                const uint32_t bh[2] = {kq.x, kq.y};
                const uint32_t bl[2] = {kq.z, kq.w};
                mma8(ac1, ah, bh); mma8(ac2, ah, bl); mma8(ac2, al, bh);
            }
#pragma unroll
            for (int j = 0; j < 4; j++) {
                const int row = rb + g + ((j >> 1) << 3);
                const int col = cb + c4 * 2 + (j & 1);
                const float m = (col < NPROB && r0 + row < NPOMO)
                              ? Mg[row * NPROB + col] : 0.f;
                const float v = (ac1[j] + ac2[j]) * isd + m;
                sm[A_S + (row * 108 + (col >> 3) * 4 + (col & 3)) * 4 + ((col >> 2) & 1)]
                    = __float_as_uint(v);
            }
        }
        __syncthreads();

        for (int r = w; r < QROWS; r += 16) {
            int offs[7];
            float vals[7];
            float mx = -INFINITY;
#pragma unroll
            for (int i = 0; i < 7; i++) {
                const int idx = lane + i * 32;
                if (idx < 208) {
                    offs[i] = A_S + (r * 108 + (idx >> 3) * 4 + (idx & 3)) * 4 + ((idx >> 2) & 1);
                    vals[i] = (idx < NNODE) ? __uint_as_float(sm[offs[i]]) : -INFINITY;
                } else { offs[i] = -1; vals[i] = -INFINITY; }
                mx = fmaxf(mx, vals[i]);
            }
#pragma unroll
            for (int o = 16; o > 0; o >>= 1) mx = fmaxf(mx, __shfl_xor_sync(~0u, mx, o));
            float sum = 0.f;
#pragma unroll
            for (int i = 0; i < 7; i++) {
                const int idx = lane + i * 32;
                vals[i] = (idx < NNODE) ? expf(vals[i] - mx) : 0.f;
                sum += vals[i];
            }
#pragma unroll
            for (int o = 16; o > 0; o >>= 1) sum += __shfl_xor_sync(~0u, sum, o);
            const float inv = 1.f / sum;
#pragma unroll
            for (int i = 0; i < 7; i++) {
                if (offs[i] < 0) continue;
                const float wv = vals[i] * inv;
                const uint32_t hi = f2tf(wv);
                sm[offs[i]]     = hi;
                sm[offs[i] + 2] = f2tf(wv - __uint_as_float(hi));
            }
        }
        __syncthreads();

        if (w < 12) {
            const int mt = w >> 2, nt = w & 3;
            const int rb = mt * 16, cb = nt * 8;
            float ac1[4] = {0.f, 0.f, 0.f, 0.f};
            float ac2[4] = {0.f, 0.f, 0.f, 0.f};
            for (int kt = 0; kt < 26; kt++) {
                const uint4 sa = *(const uint4*)&sm[A_S + ((rb + g) * 108 + kt * 4 + c4) * 4];
                const uint4 sb = *(const uint4*)&sm[A_S + ((rb + g + 8) * 108 + kt * 4 + c4) * 4];
                const uint4 vq = *(const uint4*)&sm[A_V + ((kt * 4 + c4) * 34 + cb + g) * 4];
                const uint32_t ah[4] = {sa.x, sb.x, sa.y, sb.y};
                const uint32_t al[4] = {sa.z, sb.z, sa.w, sb.w};
                const uint32_t bh[2] = {vq.x, vq.y};
                const uint32_t bl[2] = {vq.z, vq.w};
                mma8(ac1, ah, bh); mma8(ac2, ah, bl); mma8(ac2, al, bh);
            }
#pragma unroll
            for (int j = 0; j < 4; j++) {
                const int row = rb + g + ((j >> 1) << 3);
                const int col = cb + c4 * 2 + (j & 1);
                if (r0 + row < NPOMO)
                    Og[(long long)row * NEMB + col] = ac1[j] + ac2[j];
            }
        }
        __syncthreads();
    }
}

// ---------------- row softmax (final output) ----------------------------------
__global__ void __launch_bounds__(256)
softmax_kernel(float* __restrict__ X, int rows, int L, int stride)
{
    const int r = (blockIdx.x * blockDim.x + threadIdx.x) >> 5;
    const int lane = threadIdx.x & 31;
    if (r >= rows) return;
    float* rowp = X + (long long)r * stride;
    float vals[7], mx = -INFINITY;
#pragma unroll
    for (int i = 0; i < 7; i++) {
        const int idx = lane + i * 32;
        vals[i] = (idx < L) ? rowp[idx] : -INFINITY;
        mx = fmaxf(mx, vals[i]);
    }
#pragma unroll
    for (int o = 16; o > 0; o >>= 1) mx = fmaxf(mx, __shfl_xor_sync(~0u, mx, o));
    float sum = 0.f;
#pragma unroll
    for (int i = 0; i < 7; i++) {
        const int idx = lane + i * 32;
        vals[i] = (idx < L) ? expf(vals[i] - mx) : 0.f;
        sum += vals[i];
    }
#pragma unroll
    for (int o = 16; o > 0; o >>= 1) sum += __shfl_xor_sync(~0u, sum, o);
    const float inv = 1.f / sum;
#pragma unroll
    for (int i = 0; i < 7; i++) {
        const int idx = lane + i * 32;
        if (idx < L) rowp[idx] = vals[i] * inv;
    }
}

static inline int cdiv(int a, int b) { return (a + b - 1) / b; }

extern "C" void kernel_launch(void* const* d_in, const int* in_sizes, int n_in,
                              void* d_out, int out_size)
{
    const float* nodes = (const float*)d_in[0];
    const float* q1    = (const float*)d_in[1];
    const float* lastn = (const float*)d_in[2];
    const float* ninf  = (const float*)d_in[3];
    const float* Wqf   = (const float*)d_in[4];
    const float* Wql   = (const float*)d_in[5];
    const float* Wk    = (const float*)d_in[6];
    const float* Wv    = (const float*)d_in[7];
    const float* Wc    = (const float*)d_in[8];
    const float* bc    = (const float*)d_in[9];
    float* out = (float*)d_out;

    float *kbuf, *vbuf, *qbuf, *obuf, *mhbuf;
    cudaGetSymbolAddress((void**)&kbuf,  g_kbuf);
    cudaGetSymbolAddress((void**)&vbuf,  g_vbuf);
    cudaGetSymbolAddress((void**)&qbuf,  g_qbuf);
    cudaGetSymbolAddress((void**)&obuf,  g_obuf);
    cudaGetSymbolAddress((void**)&mhbuf, g_mhbuf);

    cudaFuncSetAttribute(tf32_gemm, cudaFuncAttributeMaxDynamicSharedMemorySize,
                         GEMM_SMEM_BYTES);
    cudaFuncSetAttribute(attn_kernel, cudaFuncAttributeMaxDynamicSharedMemorySize,
                         ATTN_SMEM_BYTES);

    const dim3 blk(256);
    const float ise = 0.04419417382415922f;    // 1/sqrt(512)
    const int Mn = NB * NNODE, Mq = NB * NPOMO;

    // 1) K = nodes @ Wk
    tf32_gemm<<<dim3(4, cdiv(Mn, 128), 1), blk, GEMM_SMEM_BYTES>>>(
        nodes, Wk, nullptr, nullptr, nullptr, nullptr, kbuf,
        Mn, NEMB, NEMB, NEMB, NEMB, NEMB, 0,0,0,0,0,0,0, 1, 0, 0, 0, 1.f);
    // 2) V = nodes @ Wv
    tf32_gemm<<<dim3(4, cdiv(Mn, 128), 1), blk, GEMM_SMEM_BYTES>>>(
        nodes, Wv, nullptr, nullptr, nullptr, nullptr, vbuf,
        Mn, NEMB, NEMB, NEMB, NEMB, NEMB, 0,0,0,0,0,0,0, 1, 0, 0, 0, 1.f);
    // 3) Q = q1@Wqf + lastn@Wql (dual source)
    tf32_gemm<<<dim3(4, cdiv(Mq, 128), 1), blk, GEMM_SMEM_BYTES>>>(
        q1, Wqf, lastn, Wql, nullptr, nullptr, qbuf,
        Mq, NEMB, NEMB, NEMB, NEMB, NEMB, 0,0,0,0,0,0,0, 1, 0, 0, 0, 1.f);
    // 4) fused attention: scores + mask + softmax + AV -> obuf
    attn_kernel<<<dim3(NB * NHEAD), dim3(512), ATTN_SMEM_BYTES>>>(
        qbuf, kbuf, vbuf, ninf, obuf);
    // 5) mh = O @ Wc + bc
    tf32_gemm<<<dim3(4, cdiv(Mq, 128), 1), blk, GEMM_SMEM_BYTES>>>(
        obuf, Wc, nullptr, nullptr, bc, nullptr, mhbuf,
        Mq, NEMB, NEMB, NEMB, NEMB, NEMB, 0,0,0,0,0,0,0, 1, 0, 1, 0, 1.f);
    // 6) out = 10*tanh(mh @ nodes[:,:200]^T / sqrt(EMB)) + ninf
    tf32_gemm<<<dim3(cdiv(NPROB, 128), cdiv(NPOMO, 128), NB), blk, GEMM_SMEM_BYTES>>>(
        mhbuf, nodes, nullptr, nullptr, nullptr, ninf, out,
        NPOMO, NPROB, NEMB, NEMB, NEMB, NPROB,
        (long long)NPOMO * NEMB, 0,
        (long long)NNODE * NEMB, 0,
        (long long)NPOMO * NPROB, 0,
        (long long)NPOMO * NPROB,
        1, 1, 2, NPROB, ise);
    // 7) final softmax
    {
        const int rows = NB * NPOMO;
        softmax_kernel<<<cdiv(rows, 8), blk>>>(out, rows, NPROB, NPROB);
    }
}